// round 12
// baseline (speedup 1.0000x reference)
#include <cuda_runtime.h>
#include <cuda_fp16.h>
#include <math.h>
#include <stdint.h>

#define NB 8
#define NN 2048
#define ND 128
#define BK 64
#define NIT (NN / BK)   // 32 k-chunks
#define ROWB 160u       // gemm smem row stride bytes (80 halves) -> conflict-free LDS.64
#define ZROWB 288u      // k_z smem row stride bytes: 72 mod 32 = 8, conflict-free pattern
#define NTILES 16       // gemm M-tiles per batch (128 rows each)
#define STAGEB 40960u   // per-stage bytes: A 128x160 + B 128x160
#define MBAR_OFF (3u * STAGEB)   // mbarriers after the 3 stages

// ---- scratch (__device__ globals: allocation-guard safe) ----
__device__ __half g_dist[(size_t)NB * NN * NN];   // 67 MB, k-pair-permuted, diag has +1
__device__ float  g_dinv[NB * NN];
__device__ __half g_zT[(size_t)NB * ND * NN];     // [b][d][m], permuted in m
__device__ float  g_mean[NB * ND];
__device__ float  g_rstd[NB * ND];
__device__ float2 g_part[NB * NTILES * ND];       // per-(b, n-tile) stats partials

__device__ __forceinline__ uint32_t smem_u32(const void* p) {
    uint32_t a;
    asm("{ .reg .u64 t; cvta.to.shared.u64 t, %1; cvt.u32.u64 %0, t; }" : "=r"(a) : "l"(p));
    return a;
}

// logical k within 16-block -> physical position (pair permutation so that an
// LDS.64 at 4q yields logical pairs {2q,2q+1} and {2q+8,2q+9})
__device__ __forceinline__ int kperm(int w) {
    return 4 * ((w & 7) >> 1) + ((w >> 3) << 1) + (w & 1);
}

// FMA-only sqrt (avoids MUFU throughput wall on 33.5M sqrts)
__device__ __forceinline__ float fast_sqrt(float x) {
    float xh = 0.5f * x;
    float y = __int_as_float(0x5f3759df - (__float_as_int(x) >> 1));
    y = y * (1.5f - xh * y * y);
    y = y * (1.5f - xh * y * y);
    y = y * (1.5f - xh * y * y);
    return x * y;
}

#define MBWAIT(ADDR, PH)                                                         \
    asm volatile(                                                                \
        "{\n\t.reg .pred P;\n\t"                                                 \
        "WL_%=:\n\t"                                                             \
        "mbarrier.try_wait.parity.acquire.cta.shared::cta.b64 P, [%0], %1, 0x989680;\n\t" \
        "@P bra.uni WD_%=;\n\t"                                                  \
        "bra.uni WL_%=;\n\t"                                                     \
        "WD_%=:\n\t}"                                                            \
        :: "r"(ADDR), "r"(PH) : "memory")

// ---------------------------------------------------------------------------
// Kernel 1: dist rows (fp16, permuted, +1 diag) + degree -> dinv
// ---------------------------------------------------------------------------
__global__ void k_dist(const float* __restrict__ inst) {
    int n = blockIdx.x, b = blockIdx.y;
    const float2* xb = (const float2*)(inst + (size_t)b * NN * 2);
    float2 xn = xb[n];
    float sqn = xn.x * xn.x + xn.y * xn.y;
    __half* drow = g_dist + (size_t)(b * NN + n) * NN;
    float acc = 0.f;
    for (int m = threadIdx.x; m < NN; m += 256) {
        float2 xm = xb[m];
        float sqm = xm.x * xm.x + xm.y * xm.y;
        float dot = xn.x * xm.x + xn.y * xm.y;
        float d2 = sqn + sqm - 2.f * dot;
        float d = (d2 > 0.f) ? fast_sqrt(d2) : 0.f;
        acc += d;
        float v = (m == n) ? d + 1.0f : d;   // fold self-loop into A diagonal
        drow[(m & ~15) + kperm(m & 15)] = __float2half_rn(v);
    }
    __shared__ float red[256];
    red[threadIdx.x] = acc;
    __syncthreads();
    for (int s = 128; s > 0; s >>= 1) {
        if (threadIdx.x < s) red[threadIdx.x] += red[threadIdx.x + s];
        __syncthreads();
    }
    if (threadIdx.x == 0)
        g_dinv[b * NN + n] = rsqrtf(1.0f + red[0]);
}

// ---------------------------------------------------------------------------
// Kernel 2: h0 = instance @ Wn^T + bn
// ---------------------------------------------------------------------------
__global__ void k_proj(const float* __restrict__ inst, const float* __restrict__ Wn,
                       const float* __restrict__ bn, float* __restrict__ h) {
    int idx = blockIdx.x * 256 + threadIdx.x;
    int d = idx & (ND - 1);
    int row = idx >> 7;
    float2 x = ((const float2*)inst)[row];
    h[idx] = x.x * Wn[2 * d] + x.y * Wn[2 * d + 1] + bn[d];
}

// ---------------------------------------------------------------------------
// Kernel 3 (fp16 MMA, output-major): zT[b][e][m] = dinv[m] * sum_d Wg[e,d]*h[m,d]
// Optionally fuses the PREVIOUS layer's GraphNorm during staging.
// ---------------------------------------------------------------------------
__global__ void __launch_bounds__(256) k_z(float* __restrict__ h,
                                           const float* __restrict__ Wg,
                                           int do_norm,
                                           const float* __restrict__ gnw,
                                           const float* __restrict__ gnb,
                                           const float* __restrict__ gna) {
    extern __shared__ char smc[];
    uint32_t sbase = smem_u32(smc);
    uint32_t as_ = sbase, bs_ = sbase + 128u * ZROWB;   // A=Wg, B=h
    int t = threadIdx.x, l = t & 31, wid = t >> 5;
    int wm = wid & 1, wn = wid >> 1;
    int row0 = blockIdx.x * 128;
    int b = row0 >> 11;
    int m0g = row0 & (NN - 1);

#pragma unroll
    for (int q = 0; q < 16; q++) {
        int idx = q * 256 + t;
        int r = idx >> 5, u = idx & 31;
        float4 wv = *(const float4*)&Wg[r * ND + 4 * u];
        float4 hv = *(const float4*)&h[(size_t)(row0 + r) * ND + 4 * u];
        if (do_norm) {
            float4 mw = *(const float4*)&g_mean[b * ND + 4 * u];
            float4 rw = *(const float4*)&g_rstd[b * ND + 4 * u];
            float4 w_ = *(const float4*)&gnw[4 * u];
            float4 b_ = *(const float4*)&gnb[4 * u];
            float4 a_ = *(const float4*)&gna[4 * u];
            hv.x = w_.x * (hv.x - a_.x * mw.x) * rw.x + b_.x;
            hv.y = w_.y * (hv.y - a_.y * mw.y) * rw.y + b_.y;
            hv.z = w_.z * (hv.z - a_.z * mw.z) * rw.z + b_.z;
            hv.w = w_.w * (hv.w - a_.w * mw.w) * rw.w + b_.w;
            *(float4*)&h[(size_t)(row0 + r) * ND + 4 * u] = hv;
        }
        int blk = u >> 2;
        int p0 = 2 * (u & 3), p1 = p0 + 1;
        int s0 = (p0 < 4) ? 2 * p0 : 2 * (p0 - 4) + 1;
        int s1 = (p1 < 4) ? 2 * p1 : 2 * (p1 - 4) + 1;
        uint32_t base = (uint32_t)(r * ZROWB + blk * 32);
        *(__half2*)(smc + base + s0 * 4) = __floats2half2_rn(wv.x, wv.y);
        *(__half2*)(smc + base + s1 * 4) = __floats2half2_rn(wv.z, wv.w);
        *(__half2*)(smc + 128u * ZROWB + base + s0 * 4) = __floats2half2_rn(hv.x, hv.y);
        *(__half2*)(smc + 128u * ZROWB + base + s1 * 4) = __floats2half2_rn(hv.z, hv.w);
    }
    __syncthreads();

    float c[4][4][4];
#pragma unroll
    for (int i = 0; i < 4; i++)
#pragma unroll
        for (int j = 0; j < 4; j++)
#pragma unroll
            for (int k = 0; k < 4; k++) c[i][j][k] = 0.f;

#pragma unroll
    for (int s = 0; s < 8; s++) {
        uint32_t bf[4][2];
#pragma unroll
        for (int nt = 0; nt < 4; nt++) {
            int nrow = wn * 32 + nt * 8 + (l >> 2);
            asm volatile("ld.shared.v2.b32 {%0,%1}, [%2];"
                         : "=r"(bf[nt][0]), "=r"(bf[nt][1])
                         : "r"(bs_ + (uint32_t)(nrow * ZROWB + s * 32 + (l & 3) * 8)));
        }
#pragma unroll
        for (int mt = 0; mt < 4; mt++) {
            uint32_t af[4];
            int mrow = wm * 64 + mt * 16 + (l >> 2);
            asm volatile("ld.shared.v2.b32 {%0,%1}, [%2];"
                         : "=r"(af[0]), "=r"(af[2])
                         : "r"(as_ + (uint32_t)(mrow * ZROWB + s * 32 + (l & 3) * 8)));
            asm volatile("ld.shared.v2.b32 {%0,%1}, [%2];"
                         : "=r"(af[1]), "=r"(af[3])
                         : "r"(as_ + (uint32_t)((mrow + 8) * ZROWB + s * 32 + (l & 3) * 8)));
#pragma unroll
            for (int nt = 0; nt < 4; nt++) {
                asm volatile(
                    "mma.sync.aligned.m16n8k16.row.col.f32.f16.f16.f32 "
                    "{%0,%1,%2,%3}, {%4,%5,%6,%7}, {%8,%9}, {%0,%1,%2,%3};"
                    : "+f"(c[mt][nt][0]), "+f"(c[mt][nt][1]),
                      "+f"(c[mt][nt][2]), "+f"(c[mt][nt][3])
                    : "r"(af[0]), "r"(af[1]), "r"(af[2]), "r"(af[3]),
                      "r"(bf[nt][0]), "r"(bf[nt][1]));
            }
        }
    }

    float2 dv[4];
#pragma unroll
    for (int nt = 0; nt < 4; nt++)
        dv[nt] = *(const float2*)&g_dinv[b * NN + m0g + wn * 32 + nt * 8 + 2 * (l & 3)];

    __syncthreads();
#pragma unroll
    for (int mt = 0; mt < 4; mt++) {
        int e0 = wm * 64 + mt * 16 + (l >> 2);
#pragma unroll
        for (int nt = 0; nt < 4; nt++) {
            int mloc = wn * 32 + nt * 8 + 2 * (l & 3);
            int phys = (mloc & ~15) + kperm(mloc & 15);
            *(__half2*)(smc + (uint32_t)(e0 * ZROWB + phys * 2)) =
                __floats2half2_rn(c[mt][nt][0] * dv[nt].x, c[mt][nt][1] * dv[nt].y);
            *(__half2*)(smc + (uint32_t)((e0 + 8) * ZROWB + phys * 2)) =
                __floats2half2_rn(c[mt][nt][2] * dv[nt].x, c[mt][nt][3] * dv[nt].y);
        }
    }
    __syncthreads();

    __half* zTb = g_zT + (size_t)b * ND * NN;
#pragma unroll
    for (int it = 0; it < 8; it++) {
        int idx = it * 256 + t;
        int e = idx >> 4, ch = idx & 15;
        uint4 v = *(const uint4*)(smc + (uint32_t)(e * ZROWB + ch * 16));
        *(uint4*)(zTb + (size_t)e * NN + m0g + ch * 8) = v;
    }
}

// ---------------------------------------------------------------------------
// Kernel 4: fp16 m16n8k16 mma.sync GEMM, MT=128, 256 threads (8 warps 2x4,
// warp tile 64x32 — best measured config), cp.async.bulk loader (256x128B
// copies/chunk instead of 2048x16B cp.asyncs), mbarrier completion.
// h[n,:] = tanh( dinv[n]*((dist+I)[n,:] @ z) + bg ) + h[n,:]
// Fused GraphNorm stats partials in the epilogue.
// ---------------------------------------------------------------------------
__global__ void __launch_bounds__(256) k_gemm_mma(float* __restrict__ h,
                                                  const float* __restrict__ bg_l) {
    extern __shared__ char smc[];
    uint32_t sbase = smem_u32(smc);
    int t = threadIdx.x, l = t & 31, wid = t >> 5;
    int wm = wid & 1, wn = wid >> 1;
    int b = blockIdx.y, n0 = blockIdx.x * 128;
    const __half* Ab = g_dist + ((size_t)b * NN + n0) * NN;
    const __half* Bt = g_zT + (size_t)b * ND * NN;
    uint32_t mb[3] = { sbase + MBAR_OFF, sbase + MBAR_OFF + 8, sbase + MBAR_OFF + 16 };

    if (t == 0) {
        asm volatile("mbarrier.init.shared.b64 [%0], 1;" :: "r"(mb[0]) : "memory");
        asm volatile("mbarrier.init.shared.b64 [%0], 1;" :: "r"(mb[1]) : "memory");
        asm volatile("mbarrier.init.shared.b64 [%0], 1;" :: "r"(mb[2]) : "memory");
    }
    __syncthreads();

    float c[4][4][4];
#pragma unroll
    for (int i = 0; i < 4; i++)
#pragma unroll
        for (int j = 0; j < 4; j++)
#pragma unroll
            for (int k = 0; k < 4; k++) c[i][j][k] = 0.f;

    // thread t copies one 128B row: t<128 -> A row t; t>=128 -> B row t-128
    const __half* srow = (t < 128) ? (Ab + (size_t)t * NN)
                                   : (Bt + (size_t)(t - 128) * NN);
    uint32_t drow_off = (t < 128) ? (uint32_t)t * ROWB
                                  : 20480u + (uint32_t)(t - 128) * ROWB;

#define LOADT(P, K0)                                                             \
    {                                                                            \
        if (t == 0)                                                              \
            asm volatile("mbarrier.arrive.expect_tx.shared::cta.b64 _, [%0], %1;"\
                         :: "r"(mb[P]), "r"(32768u) : "memory");                 \
        asm volatile("cp.async.bulk.shared::cta.global.mbarrier::complete_tx::bytes " \
                     "[%0], [%1], %2, [%3];"                                     \
                     :: "r"(sbase + (P) * STAGEB + drow_off),                    \
                        "l"(srow + (K0)), "r"(128u), "r"(mb[P]) : "memory");     \
    }

#define COMPUTE(P)                                                               \
    {                                                                            \
        uint32_t as_ = sbase + (P) * STAGEB;                                     \
        uint32_t bs_ = as_ + 20480u;                                             \
        _Pragma("unroll")                                                        \
        for (int s = 0; s < 4; s++) {                                            \
            uint32_t bf[4][2];                                                   \
            _Pragma("unroll")                                                    \
            for (int nt = 0; nt < 4; nt++) {                                     \
                int nrow = wn * 32 + nt * 8 + (l >> 2);                          \
                asm volatile("ld.shared.v2.b32 {%0,%1}, [%2];"                   \
                             : "=r"(bf[nt][0]), "=r"(bf[nt][1])                  \
                             : "r"(bs_ + (uint32_t)(nrow * ROWB + s * 32 + (l & 3) * 8))); \
            }                                                                    \
            _Pragma("unroll")                                                    \
            for (int mt = 0; mt < 4; mt++) {                                     \
                uint32_t af[4];                                                  \
                int mrow = wm * 64 + mt * 16 + (l >> 2);                         \
                asm volatile("ld.shared.v2.b32 {%0,%1}, [%2];"                   \
                             : "=r"(af[0]), "=r"(af[2])                          \
                             : "r"(as_ + (uint32_t)(mrow * ROWB + s * 32 + (l & 3) * 8))); \
                asm volatile("ld.shared.v2.b32 {%0,%1}, [%2];"                   \
                             : "=r"(af[1]), "=r"(af[3])                          \
                             : "r"(as_ + (uint32_t)((mrow + 8) * ROWB + s * 32 + (l & 3) * 8))); \
                _Pragma("unroll")                                                \
                for (int nt = 0; nt < 4; nt++) {                                 \
                    asm volatile(                                                \
                        "mma.sync.aligned.m16n8k16.row.col.f32.f16.f16.f32 "     \
                        "{%0,%1,%2,%3}, {%4,%5,%6,%7}, {%8,%9}, {%0,%1,%2,%3};"  \
                        : "+f"(c[mt][nt][0]), "+f"(c[mt][nt][1]),                \
                          "+f"(c[mt][nt][2]), "+f"(c[mt][nt][3])                 \
                        : "r"(af[0]), "r"(af[1]), "r"(af[2]), "r"(af[3]),        \
                          "r"(bf[nt][0]), "r"(bf[nt][1]));                       \
                }                                                                \
            }                                                                    \
        }                                                                        \
    }

    int ph[3] = {0, 0, 0};
    LOADT(0, 0);
    LOADT(1, BK);
    for (int it = 0; it < NIT; it++) {
        int st = it % 3;
        MBWAIT(mb[st], ph[st]);
        ph[st] ^= 1;
        __syncthreads();   // all warps done with COMPUTE(it-1): stage (it+2)%3 free
        if (it + 2 < NIT) {
            int pn = (it + 2) % 3;
            LOADT(pn, (it + 2) * BK);
        }
        COMPUTE(st);
    }

    // epilogue: dinv + bias + tanh + residual, accumulating stats partials
    float ssum[8], ssq[8];
#pragma unroll
    for (int j = 0; j < 8; j++) { ssum[j] = 0.f; ssq[j] = 0.f; }
#pragma unroll
    for (int mt = 0; mt < 4; mt++) {
        int r0 = n0 + wm * 64 + mt * 16 + (l >> 2);
        int r1 = r0 + 8;
        float dv0 = g_dinv[b * NN + r0];
        float dv1 = g_dinv[b * NN + r1];
#pragma unroll
        for (int nt = 0; nt < 4; nt++) {
            int cc = wn * 32 + nt * 8 + 2 * (l & 3);
            float bg0 = bg_l[cc], bg1 = bg_l[cc + 1];
            size_t h0o = ((size_t)b * NN + r0) * ND + cc;
            size_t h1o = ((size_t)b * NN + r1) * ND + cc;
            float2 hv0 = *(const float2*)&h[h0o];
            float2 hv1 = *(const float2*)&h[h1o];
            float2 o0, o1;
            o0.x = tanhf(dv0 * c[mt][nt][0] + bg0) + hv0.x;
            o0.y = tanhf(dv0 * c[mt][nt][1] + bg1) + hv0.y;
            o1.x = tanhf(dv1 * c[mt][nt][2] + bg0) + hv1.x;
            o1.y = tanhf(dv1 * c[mt][nt][3] + bg1) + hv1.y;
            *(float2*)&h[h0o] = o0;
            *(float2*)&h[h1o] = o1;
            ssum[2 * nt]     += o0.x + o1.x;
            ssum[2 * nt + 1] += o0.y + o1.y;
            ssq[2 * nt]      += o0.x * o0.x + o1.x * o1.x;
            ssq[2 * nt + 1]  += o0.y * o0.y + o1.y * o1.y;
        }
    }
#pragma unroll
    for (int off = 4; off < 32; off <<= 1)
#pragma unroll
        for (int j = 0; j < 8; j++) {
            ssum[j] += __shfl_xor_sync(0xffffffffu, ssum[j], off);
            ssq[j]  += __shfl_xor_sync(0xffffffffu, ssq[j], off);
        }
    __syncthreads();           // mainloop smem dead; reuse for cross-warp stats
    float* sp = (float*)smc;   // [0:256) sums (wm-major), [256:512) sumsqs
    if ((l >> 2) == 0) {
#pragma unroll
        for (int j = 0; j < 8; j++) {
            int col = wn * 32 + (j >> 1) * 8 + 2 * (l & 3) + (j & 1);
            sp[wm * 128 + col] = ssum[j];
            sp[256 + wm * 128 + col] = ssq[j];
        }
    }
    __syncthreads();
    if (t < 128) {
        float s = sp[t] + sp[128 + t];
        float q = sp[256 + t] + sp[384 + t];
        g_part[((size_t)b * NTILES + blockIdx.x) * ND + t] = make_float2(s, q);
    }
#undef LOADT
#undef COMPUTE
}

// ---------------------------------------------------------------------------
// Kernel 5: finalize GraphNorm stats from NTILES per-tile partials
// ---------------------------------------------------------------------------
__global__ void k_fin(const float* __restrict__ gna) {
    int b = blockIdx.x, d = threadIdx.x;
    float s = 0.f, q = 0.f;
#pragma unroll
    for (int tile = 0; tile < NTILES; tile++) {
        float2 v = g_part[((size_t)b * NTILES + tile) * ND + d];
        s += v.x; q += v.y;
    }
    float mean = s * (1.f / NN);
    float eh2 = q * (1.f / NN);
    float a = gna[d];
    float var = eh2 - (2.f * a - a * a) * mean * mean;
    g_mean[b * ND + d] = mean;
    g_rstd[b * ND + d] = rsqrtf(var + 1e-5f);
}

// ---------------------------------------------------------------------------
// Kernel 6: normalize in place (final layer only; layers 0,1 fused into k_z)
// ---------------------------------------------------------------------------
__global__ void k_norm(float* __restrict__ h, const float* __restrict__ gnw,
                       const float* __restrict__ gnb, const float* __restrict__ gna) {
    int idx = blockIdx.x * 256 + threadIdx.x;
    int d = idx & (ND - 1);
    int b = idx >> 18;
    float m = g_mean[b * ND + d];
    float rs = g_rstd[b * ND + d];
    float v = h[idx];
    h[idx] = gnw[d] * (v - gna[d] * m) * rs + gnb[d];
}

// ---------------------------------------------------------------------------
extern "C" void kernel_launch(void* const* d_in, const int* in_sizes, int n_in,
                              void* d_out, int out_size) {
    const float* inst = (const float*)d_in[0];
    const float* Wn   = (const float*)d_in[1];
    const float* bn   = (const float*)d_in[2];
    const float* Wg   = (const float*)d_in[3];
    const float* bg   = (const float*)d_in[4];
    const float* gnw  = (const float*)d_in[5];
    const float* gnb  = (const float*)d_in[6];
    const float* gna  = (const float*)d_in[7];
    float* h = (float*)d_out;

    const int SMEM_GEMM = 3 * (int)STAGEB + 32;  // stages + mbarriers
    const int SMEM_Z    = 2 * 128 * (int)ZROWB;  // 72 KB
    static int smem_set = 0;
    if (!smem_set) {
        cudaFuncSetAttribute(k_gemm_mma, cudaFuncAttributeMaxDynamicSharedMemorySize, SMEM_GEMM);
        cudaFuncSetAttribute(k_z, cudaFuncAttributeMaxDynamicSharedMemorySize, SMEM_Z);
        smem_set = 1;
    }

    k_dist<<<dim3(NN, NB), 256>>>(inst);
    k_proj<<<(NB * NN * ND) / 256, 256>>>(inst, Wn, bn, h);
    for (int l = 0; l < 3; l++) {
        // layers 1,2: fuse previous layer's GraphNorm into k_z's staging pass
        k_z<<<NB * NN / 128, 256, SMEM_Z>>>(h, Wg + l * ND * ND,
                                            l > 0 ? 1 : 0, gnw, gnb, gna);
        k_gemm_mma<<<dim3(NTILES, NB), 256, SMEM_GEMM>>>(h, bg + l * ND);
        k_fin<<<NB, ND>>>(gna);
    }
    k_norm<<<(NB * NN * ND) / 256, 256>>>(h, gnw, gnb, gna);
}

// round 13
// speedup vs baseline: 1.3758x; 1.3758x over previous
#include <cuda_runtime.h>
#include <cuda_fp16.h>
#include <math.h>
#include <stdint.h>

#define NB 8
#define NN 2048
#define ND 128
#define BK 64
#define NIT (NN / BK)   // 32 k-chunks
#define ROWB 160u       // gemm smem row stride bytes (80 halves) -> conflict-free LDS.64
#define ZROWB 288u      // k_z smem row stride bytes: 72 mod 32 = 8, conflict-free pattern
#define NTILES 16       // gemm M-tiles per batch (128 rows each)

// ---- scratch (__device__ globals: allocation-guard safe) ----
__device__ __half g_dist[(size_t)NB * NN * NN];   // 67 MB, k-pair-permuted, diag has +1
__device__ float  g_dinv[NB * NN];
__device__ __half g_zT[(size_t)NB * ND * NN];     // [b][d][m], permuted in m
__device__ float  g_mean[NB * ND];
__device__ float  g_rstd[NB * ND];
__device__ float2 g_part[NB * NTILES * ND];       // per-(b, n-tile) stats partials

__device__ __forceinline__ uint32_t smem_u32(const void* p) {
    uint32_t a;
    asm("{ .reg .u64 t; cvta.to.shared.u64 t, %1; cvt.u32.u64 %0, t; }" : "=r"(a) : "l"(p));
    return a;
}

// logical k within 16-block -> physical position (pair permutation so that an
// LDS.64 at 4q yields logical pairs {2q,2q+1} and {2q+8,2q+9})
__device__ __forceinline__ int kperm(int w) {
    return 4 * ((w & 7) >> 1) + ((w >> 3) << 1) + (w & 1);
}

// FMA-only sqrt: bit-trick rsqrt + 2 Newton iterations (~4e-6 rel err, far
// below the fp16 storage rounding of 5e-4). Avoids the MUFU throughput wall.
__device__ __forceinline__ float fast_sqrt(float x) {
    float xh = 0.5f * x;
    float y = __int_as_float(0x5f3759df - (__float_as_int(x) >> 1));
    y = y * (1.5f - xh * y * y);
    y = y * (1.5f - xh * y * y);
    return x * y;
}

// ---------------------------------------------------------------------------
// Kernel 1: dist rows (fp16, permuted, +1 diag) + degree -> dinv
// ---------------------------------------------------------------------------
__global__ void k_dist(const float* __restrict__ inst) {
    int n = blockIdx.x, b = blockIdx.y;
    const float2* xb = (const float2*)(inst + (size_t)b * NN * 2);
    float2 xn = xb[n];
    float sqn = xn.x * xn.x + xn.y * xn.y;
    __half* drow = g_dist + (size_t)(b * NN + n) * NN;
    float acc = 0.f;
    for (int m = threadIdx.x; m < NN; m += 256) {
        float2 xm = xb[m];
        float sqm = xm.x * xm.x + xm.y * xm.y;
        float dot = xn.x * xm.x + xn.y * xm.y;
        float d2 = sqn + sqm - 2.f * dot;
        float d = (d2 > 0.f) ? fast_sqrt(d2) : 0.f;
        acc += d;
        float v = (m == n) ? d + 1.0f : d;   // fold self-loop into A diagonal
        drow[(m & ~15) + kperm(m & 15)] = __float2half_rn(v);
    }
    __shared__ float red[256];
    red[threadIdx.x] = acc;
    __syncthreads();
    for (int s = 128; s > 0; s >>= 1) {
        if (threadIdx.x < s) red[threadIdx.x] += red[threadIdx.x + s];
        __syncthreads();
    }
    if (threadIdx.x == 0)
        g_dinv[b * NN + n] = rsqrtf(1.0f + red[0]);
}

// ---------------------------------------------------------------------------
// Kernel 2: h0 = instance @ Wn^T + bn
// ---------------------------------------------------------------------------
__global__ void k_proj(const float* __restrict__ inst, const float* __restrict__ Wn,
                       const float* __restrict__ bn, float* __restrict__ h) {
    int idx = blockIdx.x * 256 + threadIdx.x;
    int d = idx & (ND - 1);
    int row = idx >> 7;
    float2 x = ((const float2*)inst)[row];
    h[idx] = x.x * Wn[2 * d] + x.y * Wn[2 * d + 1] + bn[d];
}

// ---------------------------------------------------------------------------
// Kernel 3 (fp16 MMA, output-major): zT[b][e][m] = dinv[m] * sum_d Wg[e,d]*h[m,d]
// Optionally fuses the PREVIOUS layer's GraphNorm during staging.
// ---------------------------------------------------------------------------
__global__ void __launch_bounds__(256) k_z(float* __restrict__ h,
                                           const float* __restrict__ Wg,
                                           int do_norm,
                                           const float* __restrict__ gnw,
                                           const float* __restrict__ gnb,
                                           const float* __restrict__ gna) {
    extern __shared__ char smc[];
    uint32_t sbase = smem_u32(smc);
    uint32_t as_ = sbase, bs_ = sbase + 128u * ZROWB;   // A=Wg, B=h
    int t = threadIdx.x, l = t & 31, wid = t >> 5;
    int wm = wid & 1, wn = wid >> 1;
    int row0 = blockIdx.x * 128;
    int b = row0 >> 11;
    int m0g = row0 & (NN - 1);

#pragma unroll
    for (int q = 0; q < 16; q++) {
        int idx = q * 256 + t;
        int r = idx >> 5, u = idx & 31;
        float4 wv = *(const float4*)&Wg[r * ND + 4 * u];
        float4 hv = *(const float4*)&h[(size_t)(row0 + r) * ND + 4 * u];
        if (do_norm) {
            float4 mw = *(const float4*)&g_mean[b * ND + 4 * u];
            float4 rw = *(const float4*)&g_rstd[b * ND + 4 * u];
            float4 w_ = *(const float4*)&gnw[4 * u];
            float4 b_ = *(const float4*)&gnb[4 * u];
            float4 a_ = *(const float4*)&gna[4 * u];
            hv.x = w_.x * (hv.x - a_.x * mw.x) * rw.x + b_.x;
            hv.y = w_.y * (hv.y - a_.y * mw.y) * rw.y + b_.y;
            hv.z = w_.z * (hv.z - a_.z * mw.z) * rw.z + b_.z;
            hv.w = w_.w * (hv.w - a_.w * mw.w) * rw.w + b_.w;
            *(float4*)&h[(size_t)(row0 + r) * ND + 4 * u] = hv;
        }
        int blk = u >> 2;
        int p0 = 2 * (u & 3), p1 = p0 + 1;
        int s0 = (p0 < 4) ? 2 * p0 : 2 * (p0 - 4) + 1;
        int s1 = (p1 < 4) ? 2 * p1 : 2 * (p1 - 4) + 1;
        uint32_t base = (uint32_t)(r * ZROWB + blk * 32);
        *(__half2*)(smc + base + s0 * 4) = __floats2half2_rn(wv.x, wv.y);
        *(__half2*)(smc + base + s1 * 4) = __floats2half2_rn(wv.z, wv.w);
        *(__half2*)(smc + 128u * ZROWB + base + s0 * 4) = __floats2half2_rn(hv.x, hv.y);
        *(__half2*)(smc + 128u * ZROWB + base + s1 * 4) = __floats2half2_rn(hv.z, hv.w);
    }
    __syncthreads();

    float c[4][4][4];
#pragma unroll
    for (int i = 0; i < 4; i++)
#pragma unroll
        for (int j = 0; j < 4; j++)
#pragma unroll
            for (int k = 0; k < 4; k++) c[i][j][k] = 0.f;

#pragma unroll
    for (int s = 0; s < 8; s++) {
        uint32_t bf[4][2];
#pragma unroll
        for (int nt = 0; nt < 4; nt++) {
            int nrow = wn * 32 + nt * 8 + (l >> 2);
            asm volatile("ld.shared.v2.b32 {%0,%1}, [%2];"
                         : "=r"(bf[nt][0]), "=r"(bf[nt][1])
                         : "r"(bs_ + (uint32_t)(nrow * ZROWB + s * 32 + (l & 3) * 8)));
        }
#pragma unroll
        for (int mt = 0; mt < 4; mt++) {
            uint32_t af[4];
            int mrow = wm * 64 + mt * 16 + (l >> 2);
            asm volatile("ld.shared.v2.b32 {%0,%1}, [%2];"
                         : "=r"(af[0]), "=r"(af[2])
                         : "r"(as_ + (uint32_t)(mrow * ZROWB + s * 32 + (l & 3) * 8)));
            asm volatile("ld.shared.v2.b32 {%0,%1}, [%2];"
                         : "=r"(af[1]), "=r"(af[3])
                         : "r"(as_ + (uint32_t)((mrow + 8) * ZROWB + s * 32 + (l & 3) * 8)));
#pragma unroll
            for (int nt = 0; nt < 4; nt++) {
                asm volatile(
                    "mma.sync.aligned.m16n8k16.row.col.f32.f16.f16.f32 "
                    "{%0,%1,%2,%3}, {%4,%5,%6,%7}, {%8,%9}, {%0,%1,%2,%3};"
                    : "+f"(c[mt][nt][0]), "+f"(c[mt][nt][1]),
                      "+f"(c[mt][nt][2]), "+f"(c[mt][nt][3])
                    : "r"(af[0]), "r"(af[1]), "r"(af[2]), "r"(af[3]),
                      "r"(bf[nt][0]), "r"(bf[nt][1]));
            }
        }
    }

    float2 dv[4];
#pragma unroll
    for (int nt = 0; nt < 4; nt++)
        dv[nt] = *(const float2*)&g_dinv[b * NN + m0g + wn * 32 + nt * 8 + 2 * (l & 3)];

    __syncthreads();
#pragma unroll
    for (int mt = 0; mt < 4; mt++) {
        int e0 = wm * 64 + mt * 16 + (l >> 2);
#pragma unroll
        for (int nt = 0; nt < 4; nt++) {
            int mloc = wn * 32 + nt * 8 + 2 * (l & 3);
            int phys = (mloc & ~15) + kperm(mloc & 15);
            *(__half2*)(smc + (uint32_t)(e0 * ZROWB + phys * 2)) =
                __floats2half2_rn(c[mt][nt][0] * dv[nt].x, c[mt][nt][1] * dv[nt].y);
            *(__half2*)(smc + (uint32_t)((e0 + 8) * ZROWB + phys * 2)) =
                __floats2half2_rn(c[mt][nt][2] * dv[nt].x, c[mt][nt][3] * dv[nt].y);
        }
    }
    __syncthreads();

    __half* zTb = g_zT + (size_t)b * ND * NN;
#pragma unroll
    for (int it = 0; it < 8; it++) {
        int idx = it * 256 + t;
        int e = idx >> 4, ch = idx & 15;
        uint4 v = *(const uint4*)(smc + (uint32_t)(e * ZROWB + ch * 16));
        *(uint4*)(zTb + (size_t)e * NN + m0g + ch * 8) = v;
    }
}

// ---------------------------------------------------------------------------
// Kernel 4: fp16 m16n8k16 mma.sync GEMM — exact R9 best config (256 threads,
// 8 warps 2x4, warp tile 64x32, BK=64, 3-stage cp.async) + fused stats.
// h[n,:] = tanh( dinv[n]*((dist+I)[n,:] @ z) + bg ) + h[n,:]
// ---------------------------------------------------------------------------
__global__ void __launch_bounds__(256) k_gemm_mma(float* __restrict__ h,
                                                  const float* __restrict__ bg_l) {
    extern __shared__ char smc[];
    uint32_t sbase = smem_u32(smc);
    int t = threadIdx.x, l = t & 31, wid = t >> 5;
    int wm = wid & 1, wn = wid >> 1;
    int b = blockIdx.y, n0 = blockIdx.x * 128;
    const __half* Ab = g_dist + ((size_t)b * NN + n0) * NN;
    const __half* Bt = g_zT + (size_t)b * ND * NN;

    float c[4][4][4];
#pragma unroll
    for (int i = 0; i < 4; i++)
#pragma unroll
        for (int j = 0; j < 4; j++)
#pragma unroll
            for (int k = 0; k < 4; k++) c[i][j][k] = 0.f;

#define LOADT(P, K0)                                                             \
    {                                                                            \
        uint32_t xas = sbase + (P) * 40960u;                                     \
        uint32_t xbs = xas + 20480u;                                             \
        _Pragma("unroll")                                                        \
        for (int q = 0; q < 4; q++) {                                            \
            int idx = q * 256 + t;                                               \
            int r_ = idx >> 3;                                                   \
            int c16 = idx & 7;                                                   \
            uint32_t so = (uint32_t)(r_ * ROWB + c16 * 16);                      \
            asm volatile("cp.async.cg.shared.global [%0], [%1], 16;"             \
                         :: "r"(xas + so), "l"(Ab + (size_t)r_ * NN + (K0) + c16 * 8)); \
            asm volatile("cp.async.cg.shared.global [%0], [%1], 16;"             \
                         :: "r"(xbs + so), "l"(Bt + (size_t)r_ * NN + (K0) + c16 * 8)); \
        }                                                                        \
        asm volatile("cp.async.commit_group;");                                  \
    }

#define COMPUTE(P)                                                               \
    {                                                                            \
        uint32_t as_ = sbase + (P) * 40960u;                                     \
        uint32_t bs_ = as_ + 20480u;                                             \
        _Pragma("unroll")                                                        \
        for (int s = 0; s < 4; s++) {                                            \
            uint32_t bf[4][2];                                                   \
            _Pragma("unroll")                                                    \
            for (int nt = 0; nt < 4; nt++) {                                     \
                int nrow = wn * 32 + nt * 8 + (l >> 2);                          \
                asm volatile("ld.shared.v2.b32 {%0,%1}, [%2];"                   \
                             : "=r"(bf[nt][0]), "=r"(bf[nt][1])                  \
                             : "r"(bs_ + (uint32_t)(nrow * ROWB + s * 32 + (l & 3) * 8))); \
            }                                                                    \
            _Pragma("unroll")                                                    \
            for (int mt = 0; mt < 4; mt++) {                                     \
                uint32_t af[4];                                                  \
                int mrow = wm * 64 + mt * 16 + (l >> 2);                         \
                asm volatile("ld.shared.v2.b32 {%0,%1}, [%2];"                   \
                             : "=r"(af[0]), "=r"(af[2])                          \
                             : "r"(as_ + (uint32_t)(mrow * ROWB + s * 32 + (l & 3) * 8))); \
                asm volatile("ld.shared.v2.b32 {%0,%1}, [%2];"                   \
                             : "=r"(af[1]), "=r"(af[3])                          \
                             : "r"(as_ + (uint32_t)((mrow + 8) * ROWB + s * 32 + (l & 3) * 8))); \
                _Pragma("unroll")                                                \
                for (int nt = 0; nt < 4; nt++) {                                 \
                    asm volatile(                                                \
                        "mma.sync.aligned.m16n8k16.row.col.f32.f16.f16.f32 "     \
                        "{%0,%1,%2,%3}, {%4,%5,%6,%7}, {%8,%9}, {%0,%1,%2,%3};"  \
                        : "+f"(c[mt][nt][0]), "+f"(c[mt][nt][1]),                \
                          "+f"(c[mt][nt][2]), "+f"(c[mt][nt][3])                 \
                        : "r"(af[0]), "r"(af[1]), "r"(af[2]), "r"(af[3]),        \
                          "r"(bf[nt][0]), "r"(bf[nt][1]));                       \
                }                                                                \
            }                                                                    \
        }                                                                        \
    }

    LOADT(0, 0);
    LOADT(1, BK);
    int p = 0;
    for (int it = 0; it < NIT; it++) {
        if (it + 1 < NIT)
            asm volatile("cp.async.wait_group 1;");
        else
            asm volatile("cp.async.wait_group 0;");
        __syncthreads();
        if (it + 2 < NIT) {
            int pn = (it + 2) % 3;
            LOADT(pn, (it + 2) * BK);
        }
        COMPUTE(p);
        p = (p + 1) % 3;
    }

    // epilogue: dinv + bias + tanh + residual, accumulating stats partials
    float ssum[8], ssq[8];
#pragma unroll
    for (int j = 0; j < 8; j++) { ssum[j] = 0.f; ssq[j] = 0.f; }
#pragma unroll
    for (int mt = 0; mt < 4; mt++) {
        int r0 = n0 + wm * 64 + mt * 16 + (l >> 2);
        int r1 = r0 + 8;
        float dv0 = g_dinv[b * NN + r0];
        float dv1 = g_dinv[b * NN + r1];
#pragma unroll
        for (int nt = 0; nt < 4; nt++) {
            int cc = wn * 32 + nt * 8 + 2 * (l & 3);
            float bg0 = bg_l[cc], bg1 = bg_l[cc + 1];
            size_t h0o = ((size_t)b * NN + r0) * ND + cc;
            size_t h1o = ((size_t)b * NN + r1) * ND + cc;
            float2 hv0 = *(const float2*)&h[h0o];
            float2 hv1 = *(const float2*)&h[h1o];
            float2 o0, o1;
            o0.x = tanhf(dv0 * c[mt][nt][0] + bg0) + hv0.x;
            o0.y = tanhf(dv0 * c[mt][nt][1] + bg1) + hv0.y;
            o1.x = tanhf(dv1 * c[mt][nt][2] + bg0) + hv1.x;
            o1.y = tanhf(dv1 * c[mt][nt][3] + bg1) + hv1.y;
            *(float2*)&h[h0o] = o0;
            *(float2*)&h[h1o] = o1;
            ssum[2 * nt]     += o0.x + o1.x;
            ssum[2 * nt + 1] += o0.y + o1.y;
            ssq[2 * nt]      += o0.x * o0.x + o1.x * o1.x;
            ssq[2 * nt + 1]  += o0.y * o0.y + o1.y * o1.y;
        }
    }
#pragma unroll
    for (int off = 4; off < 32; off <<= 1)
#pragma unroll
        for (int j = 0; j < 8; j++) {
            ssum[j] += __shfl_xor_sync(0xffffffffu, ssum[j], off);
            ssq[j]  += __shfl_xor_sync(0xffffffffu, ssq[j], off);
        }
    __syncthreads();           // mainloop smem dead; reuse for cross-warp stats
    float* sp = (float*)smc;   // [0:256) sums (wm-major), [256:512) sumsqs
    if ((l >> 2) == 0) {
#pragma unroll
        for (int j = 0; j < 8; j++) {
            int col = wn * 32 + (j >> 1) * 8 + 2 * (l & 3) + (j & 1);
            sp[wm * 128 + col] = ssum[j];
            sp[256 + wm * 128 + col] = ssq[j];
        }
    }
    __syncthreads();
    if (t < 128) {
        float s = sp[t] + sp[128 + t];
        float q = sp[256 + t] + sp[384 + t];
        g_part[((size_t)b * NTILES + blockIdx.x) * ND + t] = make_float2(s, q);
    }
#undef LOADT
#undef COMPUTE
}

// ---------------------------------------------------------------------------
// Kernel 5: finalize GraphNorm stats from NTILES per-tile partials
// ---------------------------------------------------------------------------
__global__ void k_fin(const float* __restrict__ gna) {
    int b = blockIdx.x, d = threadIdx.x;
    float s = 0.f, q = 0.f;
#pragma unroll
    for (int tile = 0; tile < NTILES; tile++) {
        float2 v = g_part[((size_t)b * NTILES + tile) * ND + d];
        s += v.x; q += v.y;
    }
    float mean = s * (1.f / NN);
    float eh2 = q * (1.f / NN);
    float a = gna[d];
    float var = eh2 - (2.f * a - a * a) * mean * mean;
    g_mean[b * ND + d] = mean;
    g_rstd[b * ND + d] = rsqrtf(var + 1e-5f);
}

// ---------------------------------------------------------------------------
// Kernel 6: normalize in place (final layer only; layers 0,1 fused into k_z)
// ---------------------------------------------------------------------------
__global__ void k_norm(float* __restrict__ h, const float* __restrict__ gnw,
                       const float* __restrict__ gnb, const float* __restrict__ gna) {
    int idx = blockIdx.x * 256 + threadIdx.x;
    int d = idx & (ND - 1);
    int b = idx >> 18;
    float m = g_mean[b * ND + d];
    float rs = g_rstd[b * ND + d];
    float v = h[idx];
    h[idx] = gnw[d] * (v - gna[d] * m) * rs + gnb[d];
}

// ---------------------------------------------------------------------------
extern "C" void kernel_launch(void* const* d_in, const int* in_sizes, int n_in,
                              void* d_out, int out_size) {
    const float* inst = (const float*)d_in[0];
    const float* Wn   = (const float*)d_in[1];
    const float* bn   = (const float*)d_in[2];
    const float* Wg   = (const float*)d_in[3];
    const float* bg   = (const float*)d_in[4];
    const float* gnw  = (const float*)d_in[5];
    const float* gnb  = (const float*)d_in[6];
    const float* gna  = (const float*)d_in[7];
    float* h = (float*)d_out;

    const int SMEM_GEMM = 3 * 40960;             // 3 stages x (A 20KB + B 20KB)
    const int SMEM_Z    = 2 * 128 * (int)ZROWB;  // 72 KB
    static int smem_set = 0;
    if (!smem_set) {
        cudaFuncSetAttribute(k_gemm_mma, cudaFuncAttributeMaxDynamicSharedMemorySize, SMEM_GEMM);
        cudaFuncSetAttribute(k_z, cudaFuncAttributeMaxDynamicSharedMemorySize, SMEM_Z);
        smem_set = 1;
    }

    k_dist<<<dim3(NN, NB), 256>>>(inst);
    k_proj<<<(NB * NN * ND) / 256, 256>>>(inst, Wn, bn, h);
    for (int l = 0; l < 3; l++) {
        // layers 1,2: fuse previous layer's GraphNorm into k_z's staging pass
        k_z<<<NB * NN / 128, 256, SMEM_Z>>>(h, Wg + l * ND * ND,
                                            l > 0 ? 1 : 0, gnw, gnb, gna);
        k_gemm_mma<<<dim3(NTILES, NB), 256, SMEM_GEMM>>>(h, bg + l * ND);
        k_fin<<<NB, ND>>>(gna);
    }
    k_norm<<<(NB * NN * ND) / 256, 256>>>(h, gnw, gnb, gna);
}

// round 14
// speedup vs baseline: 1.4009x; 1.0183x over previous
#include <cuda_runtime.h>
#include <cuda_fp16.h>
#include <math.h>
#include <stdint.h>

#define NB 8
#define NN 2048
#define ND 128
#define BK 64
#define NIT (NN / BK)   // 32 k-chunks
#define ROWB 160u       // gemm smem row stride bytes (80 halves) -> conflict-free LDS.64
#define ZROWB 288u      // k_z smem row stride bytes: 72 mod 32 = 8, conflict-free pattern
#define NTILES 16       // gemm M-tiles per batch (128 rows each)
// k_z smem layout: Wg 128 rows, h 64 rows, stats arrays
#define ZA_OFF 0u
#define ZB_OFF (128u * ZROWB)            // 36864
#define ZST_OFF (ZB_OFF + 64u * ZROWB)   // 55296
#define ZSMEM (ZST_OFF + 1024u)          // 56320

// ---- scratch (__device__ globals: allocation-guard safe) ----
__device__ __half g_dist[(size_t)NB * NN * NN];   // 67 MB, k-pair-permuted, diag has +1
__device__ float  g_dinv[NB * NN];
__device__ __half g_zT[(size_t)NB * ND * NN];     // [b][d][m], permuted in m
__device__ float  g_mean[NB * ND];
__device__ float  g_rstd[NB * ND];
__device__ float2 g_part[NB * NTILES * ND];       // per-(b, n-tile) stats partials

__device__ __forceinline__ uint32_t smem_u32(const void* p) {
    uint32_t a;
    asm("{ .reg .u64 t; cvta.to.shared.u64 t, %1; cvt.u32.u64 %0, t; }" : "=r"(a) : "l"(p));
    return a;
}

// logical k within 16-block -> physical position (pair permutation so that an
// LDS.64 at 4q yields logical pairs {2q,2q+1} and {2q+8,2q+9})
__device__ __forceinline__ int kperm(int w) {
    return 4 * ((w & 7) >> 1) + ((w >> 3) << 1) + (w & 1);
}

// FMA-only sqrt: bit-trick rsqrt + 2 Newton iterations (~4e-6 rel err, far
// below the fp16 storage rounding of 5e-4). Avoids the MUFU throughput wall.
__device__ __forceinline__ float fast_sqrt(float x) {
    float xh = 0.5f * x;
    float y = __int_as_float(0x5f3759df - (__float_as_int(x) >> 1));
    y = y * (1.5f - xh * y * y);
    y = y * (1.5f - xh * y * y);
    return x * y;
}

// ---------------------------------------------------------------------------
// Kernel 1: dist rows (fp16, permuted, +1 diag) + degree -> dinv
// ---------------------------------------------------------------------------
__global__ void k_dist(const float* __restrict__ inst) {
    int n = blockIdx.x, b = blockIdx.y;
    const float2* xb = (const float2*)(inst + (size_t)b * NN * 2);
    float2 xn = xb[n];
    float sqn = xn.x * xn.x + xn.y * xn.y;
    __half* drow = g_dist + (size_t)(b * NN + n) * NN;
    float acc = 0.f;
    for (int m = threadIdx.x; m < NN; m += 256) {
        float2 xm = xb[m];
        float sqm = xm.x * xm.x + xm.y * xm.y;
        float dot = xn.x * xm.x + xn.y * xm.y;
        float d2 = sqn + sqm - 2.f * dot;
        float d = (d2 > 0.f) ? fast_sqrt(d2) : 0.f;
        acc += d;
        float v = (m == n) ? d + 1.0f : d;   // fold self-loop into A diagonal
        drow[(m & ~15) + kperm(m & 15)] = __float2half_rn(v);
    }
    __shared__ float red[256];
    red[threadIdx.x] = acc;
    __syncthreads();
    for (int s = 128; s > 0; s >>= 1) {
        if (threadIdx.x < s) red[threadIdx.x] += red[threadIdx.x + s];
        __syncthreads();
    }
    if (threadIdx.x == 0)
        g_dinv[b * NN + n] = rsqrtf(1.0f + red[0]);
}

// ---------------------------------------------------------------------------
// Kernel 3 (fp16 MMA, output-major, 64-row m-tiles, grid 256):
//   zT[b][e][m] = dinv[m] * sum_d Wg[e,d] * hn[m,d]
// mode 0 (layer 0): computes h = inst@Wn^T+bn during staging, writes h.
// mode 1 (layers 1,2): inline-finalizes prev-layer GraphNorm stats from
// g_part, normalizes h during staging, writes normalized h back.
// ---------------------------------------------------------------------------
__global__ void __launch_bounds__(256) k_z(float* __restrict__ h,
                                           const float* __restrict__ Wg,
                                           int mode,
                                           const float* __restrict__ gnw,
                                           const float* __restrict__ gnb,
                                           const float* __restrict__ gna,
                                           const float* __restrict__ inst,
                                           const float* __restrict__ Wn,
                                           const float* __restrict__ bn) {
    extern __shared__ char smc[];
    uint32_t sbase = smem_u32(smc);
    uint32_t as_ = sbase + ZA_OFF, bs_ = sbase + ZB_OFF;
    float* smean = (float*)(smc + ZST_OFF);
    float* srstd = (float*)(smc + ZST_OFF + 512);
    int t = threadIdx.x, l = t & 31, wid = t >> 5;
    int wm = wid & 3, wn = wid >> 2;   // wm: e-quarter (32), wn: m-half (32)
    int row0 = blockIdx.x * 64;        // global row over NB*NN (m dimension)
    int b = row0 >> 11;
    int m0g = row0 & (NN - 1);

    if (mode == 1) {
        // inline finalize of previous layer's GraphNorm stats (deterministic)
        if (t < 128) {
            float s = 0.f, q = 0.f;
#pragma unroll
            for (int tile = 0; tile < NTILES; tile++) {
                float2 v = g_part[((size_t)b * NTILES + tile) * ND + t];
                s += v.x; q += v.y;
            }
            float mean = s * (1.f / NN);
            float eh2 = q * (1.f / NN);
            float a = gna[t];
            float var = eh2 - (2.f * a - a * a) * mean * mean;
            smean[t] = mean;
            srstd[t] = rsqrtf(var + 1e-5f);
        }
        __syncthreads();
    }

    // stage Wg (full 128 e-rows), fp32 -> fp16 with d-pair permutation
#pragma unroll
    for (int q = 0; q < 16; q++) {
        int idx = q * 256 + t;
        int r = idx >> 5, u = idx & 31;
        float4 wv = *(const float4*)&Wg[r * ND + 4 * u];
        int blk = u >> 2;
        int p0 = 2 * (u & 3), p1 = p0 + 1;
        int s0 = (p0 < 4) ? 2 * p0 : 2 * (p0 - 4) + 1;
        int s1 = (p1 < 4) ? 2 * p1 : 2 * (p1 - 4) + 1;
        uint32_t base = (uint32_t)(r * ZROWB + blk * 32);
        *(__half2*)(smc + ZA_OFF + base + s0 * 4) = __floats2half2_rn(wv.x, wv.y);
        *(__half2*)(smc + ZA_OFF + base + s1 * 4) = __floats2half2_rn(wv.z, wv.w);
    }
    // stage h (64 m-rows) with proj or norm applied
#pragma unroll
    for (int q = 0; q < 8; q++) {
        int idx = q * 256 + t;
        int r = idx >> 5, u = idx & 31;
        int grow = row0 + r;
        float4 hv;
        if (mode == 0) {
            float2 x = ((const float2*)inst)[grow];
#pragma unroll
            for (int j = 0; j < 4; j++) {
                int d = 4 * u + j;
                ((float*)&hv)[j] = x.x * Wn[2 * d] + x.y * Wn[2 * d + 1] + bn[d];
            }
            *(float4*)&h[(size_t)grow * ND + 4 * u] = hv;
        } else {
            hv = *(const float4*)&h[(size_t)grow * ND + 4 * u];
            float4 mw = *(const float4*)&smean[4 * u];
            float4 rw = *(const float4*)&srstd[4 * u];
            float4 w_ = *(const float4*)&gnw[4 * u];
            float4 b_ = *(const float4*)&gnb[4 * u];
            float4 a_ = *(const float4*)&gna[4 * u];
            hv.x = w_.x * (hv.x - a_.x * mw.x) * rw.x + b_.x;
            hv.y = w_.y * (hv.y - a_.y * mw.y) * rw.y + b_.y;
            hv.z = w_.z * (hv.z - a_.z * mw.z) * rw.z + b_.z;
            hv.w = w_.w * (hv.w - a_.w * mw.w) * rw.w + b_.w;
            *(float4*)&h[(size_t)grow * ND + 4 * u] = hv;
        }
        int blk = u >> 2;
        int p0 = 2 * (u & 3), p1 = p0 + 1;
        int s0 = (p0 < 4) ? 2 * p0 : 2 * (p0 - 4) + 1;
        int s1 = (p1 < 4) ? 2 * p1 : 2 * (p1 - 4) + 1;
        uint32_t base = (uint32_t)(r * ZROWB + blk * 32);
        *(__half2*)(smc + ZB_OFF + base + s0 * 4) = __floats2half2_rn(hv.x, hv.y);
        *(__half2*)(smc + ZB_OFF + base + s1 * 4) = __floats2half2_rn(hv.z, hv.w);
    }
    __syncthreads();

    // MMA: output e x m = 128 x 64; warp tile 32e x 32m
    float c[2][4][4];
#pragma unroll
    for (int i = 0; i < 2; i++)
#pragma unroll
        for (int j = 0; j < 4; j++)
#pragma unroll
            for (int k = 0; k < 4; k++) c[i][j][k] = 0.f;

#pragma unroll
    for (int s = 0; s < 8; s++) {
        uint32_t bf[4][2];
#pragma unroll
        for (int nt = 0; nt < 4; nt++) {
            int nrow = wn * 32 + nt * 8 + (l >> 2);   // m rows (0..63)
            asm volatile("ld.shared.v2.b32 {%0,%1}, [%2];"
                         : "=r"(bf[nt][0]), "=r"(bf[nt][1])
                         : "r"(bs_ + (uint32_t)(nrow * ZROWB + s * 32 + (l & 3) * 8)));
        }
#pragma unroll
        for (int mt = 0; mt < 2; mt++) {
            uint32_t af[4];
            int mrow = wm * 32 + mt * 16 + (l >> 2);  // e rows (0..127)
            asm volatile("ld.shared.v2.b32 {%0,%1}, [%2];"
                         : "=r"(af[0]), "=r"(af[2])
                         : "r"(as_ + (uint32_t)(mrow * ZROWB + s * 32 + (l & 3) * 8)));
            asm volatile("ld.shared.v2.b32 {%0,%1}, [%2];"
                         : "=r"(af[1]), "=r"(af[3])
                         : "r"(as_ + (uint32_t)((mrow + 8) * ZROWB + s * 32 + (l & 3) * 8)));
#pragma unroll
            for (int nt = 0; nt < 4; nt++) {
                asm volatile(
                    "mma.sync.aligned.m16n8k16.row.col.f32.f16.f16.f32 "
                    "{%0,%1,%2,%3}, {%4,%5,%6,%7}, {%8,%9}, {%0,%1,%2,%3};"
                    : "+f"(c[mt][nt][0]), "+f"(c[mt][nt][1]),
                      "+f"(c[mt][nt][2]), "+f"(c[mt][nt][3])
                    : "r"(af[0]), "r"(af[1]), "r"(af[2]), "r"(af[3]),
                      "r"(bf[nt][0]), "r"(bf[nt][1]));
            }
        }
    }

    float2 dv[4];
#pragma unroll
    for (int nt = 0; nt < 4; nt++)
        dv[nt] = *(const float2*)&g_dinv[b * NN + m0g + wn * 32 + nt * 8 + 2 * (l & 3)];

    __syncthreads();   // all MMA reads of Wg region done; reuse as output buffer
#pragma unroll
    for (int mt = 0; mt < 2; mt++) {
        int e0 = wm * 32 + mt * 16 + (l >> 2);
#pragma unroll
        for (int nt = 0; nt < 4; nt++) {
            int mloc = wn * 32 + nt * 8 + 2 * (l & 3);
            int phys = (mloc & ~15) + kperm(mloc & 15);
            *(__half2*)(smc + ZA_OFF + (uint32_t)(e0 * ZROWB + phys * 2)) =
                __floats2half2_rn(c[mt][nt][0] * dv[nt].x, c[mt][nt][1] * dv[nt].y);
            *(__half2*)(smc + ZA_OFF + (uint32_t)((e0 + 8) * ZROWB + phys * 2)) =
                __floats2half2_rn(c[mt][nt][2] * dv[nt].x, c[mt][nt][3] * dv[nt].y);
        }
    }
    __syncthreads();

    // coalesced copy-out: 128 e-rows x 64 m-halves (128 B per row)
    __half* zTb = g_zT + (size_t)b * ND * NN;
#pragma unroll
    for (int it = 0; it < 4; it++) {
        int idx = it * 256 + t;
        int e = idx >> 3, ch = idx & 7;
        uint4 v = *(const uint4*)(smc + ZA_OFF + (uint32_t)(e * ZROWB + ch * 16));
        *(uint4*)(zTb + (size_t)e * NN + m0g + ch * 8) = v;
    }
}

// ---------------------------------------------------------------------------
// Kernel 4: fp16 m16n8k16 mma.sync GEMM — R9/R13 best config, unchanged.
// h[n,:] = tanh( dinv[n]*((dist+I)[n,:] @ z) + bg ) + h[n,:]  + fused stats.
// ---------------------------------------------------------------------------
__global__ void __launch_bounds__(256) k_gemm_mma(float* __restrict__ h,
                                                  const float* __restrict__ bg_l) {
    extern __shared__ char smc[];
    uint32_t sbase = smem_u32(smc);
    int t = threadIdx.x, l = t & 31, wid = t >> 5;
    int wm = wid & 1, wn = wid >> 1;
    int b = blockIdx.y, n0 = blockIdx.x * 128;
    const __half* Ab = g_dist + ((size_t)b * NN + n0) * NN;
    const __half* Bt = g_zT + (size_t)b * ND * NN;

    float c[4][4][4];
#pragma unroll
    for (int i = 0; i < 4; i++)
#pragma unroll
        for (int j = 0; j < 4; j++)
#pragma unroll
            for (int k = 0; k < 4; k++) c[i][j][k] = 0.f;

#define LOADT(P, K0)                                                             \
    {                                                                            \
        uint32_t xas = sbase + (P) * 40960u;                                     \
        uint32_t xbs = xas + 20480u;                                             \
        _Pragma("unroll")                                                        \
        for (int q = 0; q < 4; q++) {                                            \
            int idx = q * 256 + t;                                               \
            int r_ = idx >> 3;                                                   \
            int c16 = idx & 7;                                                   \
            uint32_t so = (uint32_t)(r_ * ROWB + c16 * 16);                      \
            asm volatile("cp.async.cg.shared.global [%0], [%1], 16;"             \
                         :: "r"(xas + so), "l"(Ab + (size_t)r_ * NN + (K0) + c16 * 8)); \
            asm volatile("cp.async.cg.shared.global [%0], [%1], 16;"             \
                         :: "r"(xbs + so), "l"(Bt + (size_t)r_ * NN + (K0) + c16 * 8)); \
        }                                                                        \
        asm volatile("cp.async.commit_group;");                                  \
    }

#define COMPUTE(P)                                                               \
    {                                                                            \
        uint32_t as_ = sbase + (P) * 40960u;                                     \
        uint32_t bs_ = as_ + 20480u;                                             \
        _Pragma("unroll")                                                        \
        for (int s = 0; s < 4; s++) {                                            \
            uint32_t bf[4][2];                                                   \
            _Pragma("unroll")                                                    \
            for (int nt = 0; nt < 4; nt++) {                                     \
                int nrow = wn * 32 + nt * 8 + (l >> 2);                          \
                asm volatile("ld.shared.v2.b32 {%0,%1}, [%2];"                   \
                             : "=r"(bf[nt][0]), "=r"(bf[nt][1])                  \
                             : "r"(bs_ + (uint32_t)(nrow * ROWB + s * 32 + (l & 3) * 8))); \
            }                                                                    \
            _Pragma("unroll")                                                    \
            for (int mt = 0; mt < 4; mt++) {                                     \
                uint32_t af[4];                                                  \
                int mrow = wm * 64 + mt * 16 + (l >> 2);                         \
                asm volatile("ld.shared.v2.b32 {%0,%1}, [%2];"                   \
                             : "=r"(af[0]), "=r"(af[2])                          \
                             : "r"(as_ + (uint32_t)(mrow * ROWB + s * 32 + (l & 3) * 8))); \
                asm volatile("ld.shared.v2.b32 {%0,%1}, [%2];"                   \
                             : "=r"(af[1]), "=r"(af[3])                          \
                             : "r"(as_ + (uint32_t)((mrow + 8) * ROWB + s * 32 + (l & 3) * 8))); \
                _Pragma("unroll")                                                \
                for (int nt = 0; nt < 4; nt++) {                                 \
                    asm volatile(                                                \
                        "mma.sync.aligned.m16n8k16.row.col.f32.f16.f16.f32 "     \
                        "{%0,%1,%2,%3}, {%4,%5,%6,%7}, {%8,%9}, {%0,%1,%2,%3};"  \
                        : "+f"(c[mt][nt][0]), "+f"(c[mt][nt][1]),                \
                          "+f"(c[mt][nt][2]), "+f"(c[mt][nt][3])                 \
                        : "r"(af[0]), "r"(af[1]), "r"(af[2]), "r"(af[3]),        \
                          "r"(bf[nt][0]), "r"(bf[nt][1]));                       \
                }                                                                \
            }                                                                    \
        }                                                                        \
    }

    LOADT(0, 0);
    LOADT(1, BK);
    int p = 0;
    for (int it = 0; it < NIT; it++) {
        if (it + 1 < NIT)
            asm volatile("cp.async.wait_group 1;");
        else
            asm volatile("cp.async.wait_group 0;");
        __syncthreads();
        if (it + 2 < NIT) {
            int pn = (it + 2) % 3;
            LOADT(pn, (it + 2) * BK);
        }
        COMPUTE(p);
        p = (p + 1) % 3;
    }

    // epilogue: dinv + bias + tanh + residual, accumulating stats partials
    float ssum[8], ssq[8];
#pragma unroll
    for (int j = 0; j < 8; j++) { ssum[j] = 0.f; ssq[j] = 0.f; }
#pragma unroll
    for (int mt = 0; mt < 4; mt++) {
        int r0 = n0 + wm * 64 + mt * 16 + (l >> 2);
        int r1 = r0 + 8;
        float dv0 = g_dinv[b * NN + r0];
        float dv1 = g_dinv[b * NN + r1];
#pragma unroll
        for (int nt = 0; nt < 4; nt++) {
            int cc = wn * 32 + nt * 8 + 2 * (l & 3);
            float bg0 = bg_l[cc], bg1 = bg_l[cc + 1];
            size_t h0o = ((size_t)b * NN + r0) * ND + cc;
            size_t h1o = ((size_t)b * NN + r1) * ND + cc;
            float2 hv0 = *(const float2*)&h[h0o];
            float2 hv1 = *(const float2*)&h[h1o];
            float2 o0, o1;
            o0.x = tanhf(dv0 * c[mt][nt][0] + bg0) + hv0.x;
            o0.y = tanhf(dv0 * c[mt][nt][1] + bg1) + hv0.y;
            o1.x = tanhf(dv1 * c[mt][nt][2] + bg0) + hv1.x;
            o1.y = tanhf(dv1 * c[mt][nt][3] + bg1) + hv1.y;
            *(float2*)&h[h0o] = o0;
            *(float2*)&h[h1o] = o1;
            ssum[2 * nt]     += o0.x + o1.x;
            ssum[2 * nt + 1] += o0.y + o1.y;
            ssq[2 * nt]      += o0.x * o0.x + o1.x * o1.x;
            ssq[2 * nt + 1]  += o0.y * o0.y + o1.y * o1.y;
        }
    }
#pragma unroll
    for (int off = 4; off < 32; off <<= 1)
#pragma unroll
        for (int j = 0; j < 8; j++) {
            ssum[j] += __shfl_xor_sync(0xffffffffu, ssum[j], off);
            ssq[j]  += __shfl_xor_sync(0xffffffffu, ssq[j], off);
        }
    __syncthreads();           // mainloop smem dead; reuse for cross-warp stats
    float* sp = (float*)smc;   // [0:256) sums (wm-major), [256:512) sumsqs
    if ((l >> 2) == 0) {
#pragma unroll
        for (int j = 0; j < 8; j++) {
            int col = wn * 32 + (j >> 1) * 8 + 2 * (l & 3) + (j & 1);
            sp[wm * 128 + col] = ssum[j];
            sp[256 + wm * 128 + col] = ssq[j];
        }
    }
    __syncthreads();
    if (t < 128) {
        float s = sp[t] + sp[128 + t];
        float q = sp[256 + t] + sp[384 + t];
        g_part[((size_t)b * NTILES + blockIdx.x) * ND + t] = make_float2(s, q);
    }
#undef LOADT
#undef COMPUTE
}

// ---------------------------------------------------------------------------
// Kernel 5: finalize GraphNorm stats (final layer only)
// ---------------------------------------------------------------------------
__global__ void k_fin(const float* __restrict__ gna) {
    int b = blockIdx.x, d = threadIdx.x;
    float s = 0.f, q = 0.f;
#pragma unroll
    for (int tile = 0; tile < NTILES; tile++) {
        float2 v = g_part[((size_t)b * NTILES + tile) * ND + d];
        s += v.x; q += v.y;
    }
    float mean = s * (1.f / NN);
    float eh2 = q * (1.f / NN);
    float a = gna[d];
    float var = eh2 - (2.f * a - a * a) * mean * mean;
    g_mean[b * ND + d] = mean;
    g_rstd[b * ND + d] = rsqrtf(var + 1e-5f);
}

// ---------------------------------------------------------------------------
// Kernel 6: normalize in place (final layer only)
// ---------------------------------------------------------------------------
__global__ void k_norm(float* __restrict__ h, const float* __restrict__ gnw,
                       const float* __restrict__ gnb, const float* __restrict__ gna) {
    int idx = blockIdx.x * 256 + threadIdx.x;
    int d = idx & (ND - 1);
    int b = idx >> 18;
    float m = g_mean[b * ND + d];
    float rs = g_rstd[b * ND + d];
    float v = h[idx];
    h[idx] = gnw[d] * (v - gna[d] * m) * rs + gnb[d];
}

// ---------------------------------------------------------------------------
extern "C" void kernel_launch(void* const* d_in, const int* in_sizes, int n_in,
                              void* d_out, int out_size) {
    const float* inst = (const float*)d_in[0];
    const float* Wn   = (const float*)d_in[1];
    const float* bn   = (const float*)d_in[2];
    const float* Wg   = (const float*)d_in[3];
    const float* bg   = (const float*)d_in[4];
    const float* gnw  = (const float*)d_in[5];
    const float* gnb  = (const float*)d_in[6];
    const float* gna  = (const float*)d_in[7];
    float* h = (float*)d_out;

    const int SMEM_GEMM = 3 * 40960;   // 3 stages x (A 20KB + B 20KB)
    const int SMEM_Z    = (int)ZSMEM;  // 56320
    static int smem_set = 0;
    if (!smem_set) {
        cudaFuncSetAttribute(k_gemm_mma, cudaFuncAttributeMaxDynamicSharedMemorySize, SMEM_GEMM);
        cudaFuncSetAttribute(k_z, cudaFuncAttributeMaxDynamicSharedMemorySize, SMEM_Z);
        smem_set = 1;
    }

    k_dist<<<dim3(NN, NB), 256>>>(inst);
    for (int l = 0; l < 3; l++) {
        k_z<<<NB * NN / 64, 256, SMEM_Z>>>(h, Wg + l * ND * ND,
                                           l == 0 ? 0 : 1, gnw, gnb, gna,
                                           inst, Wn, bn);
        k_gemm_mma<<<dim3(NTILES, NB), 256, SMEM_GEMM>>>(h, bg + l * ND);
    }
    k_fin<<<NB, ND>>>(gna);
    k_norm<<<(NB * NN * ND) / 256, 256>>>(h, gnw, gnb, gna);
}

// round 15
// speedup vs baseline: 1.4015x; 1.0005x over previous
#include <cuda_runtime.h>
#include <cuda_fp16.h>
#include <math.h>
#include <stdint.h>

#define NB 8
#define NN 2048
#define ND 128
#define BK 64
#define NIT (NN / BK)   // 32 k-chunks
#define ROWB 160u       // gemm smem row stride bytes (80 halves) -> conflict-free LDS.64
#define ZROWB 288u      // k_z smem row stride bytes: 72 mod 32 = 8, conflict-free pattern
#define NTILES 16       // gemm M-tiles per batch (128 rows each)
// k_z smem layout: Wg 128 rows, h 64 rows, stats arrays
#define ZA_OFF 0u
#define ZB_OFF (128u * ZROWB)            // 36864
#define ZST_OFF (ZB_OFF + 64u * ZROWB)   // 55296
#define ZSMEM (ZST_OFF + 1024u)          // 56320

// ---- scratch (__device__ globals: allocation-guard safe) ----
__device__ __half g_dist[(size_t)NB * NN * NN];   // 67 MB, k-pair-permuted, diag has +1
__device__ float  g_dinv[NB * NN];
__device__ __half g_zT[(size_t)NB * ND * NN];     // [b][d][m], permuted in m
__device__ float  g_mean[NB * ND];
__device__ float  g_rstd[NB * ND];
__device__ float2 g_part[NB * NTILES * ND];       // per-(b, n-tile) stats partials

__device__ __forceinline__ uint32_t smem_u32(const void* p) {
    uint32_t a;
    asm("{ .reg .u64 t; cvta.to.shared.u64 t, %1; cvt.u32.u64 %0, t; }" : "=r"(a) : "l"(p));
    return a;
}

// logical k within 16-block -> physical position (pair permutation so that an
// LDS.64 at 4q yields logical pairs {2q,2q+1} and {2q+8,2q+9})
__device__ __forceinline__ int kperm(int w) {
    return 4 * ((w & 7) >> 1) + ((w >> 3) << 1) + (w & 1);
}

// FMA-only sqrt: bit-trick rsqrt + 2 Newton iterations (~4e-6 rel err, far
// below the fp16 storage rounding of 5e-4). Avoids the MUFU throughput wall.
__device__ __forceinline__ float fast_sqrt(float x) {
    float xh = 0.5f * x;
    float y = __int_as_float(0x5f3759df - (__float_as_int(x) >> 1));
    y = y * (1.5f - xh * y * y);
    y = y * (1.5f - xh * y * y);
    return x * y;
}

// ---------------------------------------------------------------------------
// Kernel 1: dist rows (fp16, permuted, +1 diag) + degree -> dinv
// ---------------------------------------------------------------------------
__global__ void k_dist(const float* __restrict__ inst) {
    int n = blockIdx.x, b = blockIdx.y;
    const float2* xb = (const float2*)(inst + (size_t)b * NN * 2);
    float2 xn = xb[n];
    float sqn = xn.x * xn.x + xn.y * xn.y;
    __half* drow = g_dist + (size_t)(b * NN + n) * NN;
    float acc = 0.f;
    for (int m = threadIdx.x; m < NN; m += 256) {
        float2 xm = xb[m];
        float sqm = xm.x * xm.x + xm.y * xm.y;
        float dot = xn.x * xm.x + xn.y * xm.y;
        float d2 = sqn + sqm - 2.f * dot;
        float d = (d2 > 0.f) ? fast_sqrt(d2) : 0.f;
        acc += d;
        float v = (m == n) ? d + 1.0f : d;   // fold self-loop into A diagonal
        drow[(m & ~15) + kperm(m & 15)] = __float2half_rn(v);
    }
    __shared__ float red[256];
    red[threadIdx.x] = acc;
    __syncthreads();
    for (int s = 128; s > 0; s >>= 1) {
        if (threadIdx.x < s) red[threadIdx.x] += red[threadIdx.x + s];
        __syncthreads();
    }
    if (threadIdx.x == 0)
        g_dinv[b * NN + n] = rsqrtf(1.0f + red[0]);
}

// ---------------------------------------------------------------------------
// Kernel 3 (fp16 MMA, output-major, 64-row m-tiles, grid 256, 512 threads):
//   zT[b][e][m] = dinv[m] * sum_d Wg[e,d] * hn[m,d]
// Staging is register-batched: ALL 12 float4 gmem loads issued before any
// conversion (MLP=12/thread) to collapse the serial latency exposure that
// bound the 256-thread version (ncu: regs=64, all pipes idle).
// mode 0: h = inst@Wn^T+bn computed during staging; mode 1: inline stats
// finalize + GraphNorm applied during staging, normalized h written back.
// ---------------------------------------------------------------------------
__global__ void __launch_bounds__(512) k_z(float* __restrict__ h,
                                           const float* __restrict__ Wg,
                                           int mode,
                                           const float* __restrict__ gnw,
                                           const float* __restrict__ gnb,
                                           const float* __restrict__ gna,
                                           const float* __restrict__ inst,
                                           const float* __restrict__ Wn,
                                           const float* __restrict__ bn) {
    extern __shared__ char smc[];
    uint32_t sbase = smem_u32(smc);
    uint32_t as_ = sbase + ZA_OFF, bs_ = sbase + ZB_OFF;
    float* smean = (float*)(smc + ZST_OFF);
    float* srstd = (float*)(smc + ZST_OFF + 512);
    int t = threadIdx.x, l = t & 31, wid = t >> 5;
    int wm = wid & 3, wn = wid >> 2;   // wm: e-quarter (32 rows), wn: m-quarter (16 rows)
    int row0 = blockIdx.x * 64;        // global row over NB*NN (m dimension)
    int b = row0 >> 11;
    int m0g = row0 & (NN - 1);

    if (mode == 1) {
        // inline finalize of previous layer's GraphNorm stats (deterministic)
        if (t < 128) {
            float s = 0.f, q = 0.f;
#pragma unroll
            for (int tile = 0; tile < NTILES; tile++) {
                float2 v = g_part[((size_t)b * NTILES + tile) * ND + t];
                s += v.x; q += v.y;
            }
            float mean = s * (1.f / NN);
            float eh2 = q * (1.f / NN);
            float a = gna[t];
            float var = eh2 - (2.f * a - a * a) * mean * mean;
            smean[t] = mean;
            srstd[t] = rsqrtf(var + 1e-5f);
        }
        __syncthreads();
    }

    // ---- phase 1: batched gmem loads into registers (MLP = 12/thread) ----
    float4 wbuf[8];   // Wg: 128 rows x 32 float4 = 4096 / 512 thr
    float4 hbuf[4];   // h:   64 rows x 32 float4 = 2048 / 512 thr
#pragma unroll
    for (int q = 0; q < 8; q++) {
        int idx = q * 512 + t;
        wbuf[q] = *(const float4*)&Wg[(idx >> 5) * ND + 4 * (idx & 31)];
    }
    if (mode == 0) {
#pragma unroll
        for (int q = 0; q < 4; q++) {
            int idx = q * 512 + t;
            int grow = row0 + (idx >> 5), u = idx & 31;
            float2 x = ((const float2*)inst)[grow];
#pragma unroll
            for (int j = 0; j < 4; j++) {
                int d = 4 * u + j;
                ((float*)&hbuf[q])[j] = x.x * Wn[2 * d] + x.y * Wn[2 * d + 1] + bn[d];
            }
        }
    } else {
#pragma unroll
        for (int q = 0; q < 4; q++) {
            int idx = q * 512 + t;
            hbuf[q] = *(const float4*)&h[(size_t)(row0 + (idx >> 5)) * ND + 4 * (idx & 31)];
        }
    }

    // ---- phase 2: convert + permuted smem stores (and h writeback) ----
#pragma unroll
    for (int q = 0; q < 8; q++) {
        int idx = q * 512 + t;
        int r = idx >> 5, u = idx & 31;
        int blk = u >> 2;
        int p0 = 2 * (u & 3), p1 = p0 + 1;
        int s0 = (p0 < 4) ? 2 * p0 : 2 * (p0 - 4) + 1;
        int s1 = (p1 < 4) ? 2 * p1 : 2 * (p1 - 4) + 1;
        uint32_t base = (uint32_t)(r * ZROWB + blk * 32);
        *(__half2*)(smc + ZA_OFF + base + s0 * 4) = __floats2half2_rn(wbuf[q].x, wbuf[q].y);
        *(__half2*)(smc + ZA_OFF + base + s1 * 4) = __floats2half2_rn(wbuf[q].z, wbuf[q].w);
    }
#pragma unroll
    for (int q = 0; q < 4; q++) {
        int idx = q * 512 + t;
        int r = idx >> 5, u = idx & 31;
        int grow = row0 + r;
        float4 hv = hbuf[q];
        if (mode == 1) {
            float4 mw = *(const float4*)&smean[4 * u];
            float4 rw = *(const float4*)&srstd[4 * u];
            float4 w_ = *(const float4*)&gnw[4 * u];
            float4 b_ = *(const float4*)&gnb[4 * u];
            float4 a_ = *(const float4*)&gna[4 * u];
            hv.x = w_.x * (hv.x - a_.x * mw.x) * rw.x + b_.x;
            hv.y = w_.y * (hv.y - a_.y * mw.y) * rw.y + b_.y;
            hv.z = w_.z * (hv.z - a_.z * mw.z) * rw.z + b_.z;
            hv.w = w_.w * (hv.w - a_.w * mw.w) * rw.w + b_.w;
        }
        *(float4*)&h[(size_t)grow * ND + 4 * u] = hv;
        int blk = u >> 2;
        int p0 = 2 * (u & 3), p1 = p0 + 1;
        int s0 = (p0 < 4) ? 2 * p0 : 2 * (p0 - 4) + 1;
        int s1 = (p1 < 4) ? 2 * p1 : 2 * (p1 - 4) + 1;
        uint32_t base = (uint32_t)(r * ZROWB + blk * 32);
        *(__half2*)(smc + ZB_OFF + base + s0 * 4) = __floats2half2_rn(hv.x, hv.y);
        *(__half2*)(smc + ZB_OFF + base + s1 * 4) = __floats2half2_rn(hv.z, hv.w);
    }
    __syncthreads();

    // ---- MMA: output e x m = 128 x 64; 16 warps, warp tile 32e x 16m ----
    float c[2][2][4];
#pragma unroll
    for (int i = 0; i < 2; i++)
#pragma unroll
        for (int j = 0; j < 2; j++)
#pragma unroll
            for (int k = 0; k < 4; k++) c[i][j][k] = 0.f;

#pragma unroll
    for (int s = 0; s < 8; s++) {
        uint32_t bf[2][2];
#pragma unroll
        for (int nt = 0; nt < 2; nt++) {
            int nrow = wn * 16 + nt * 8 + (l >> 2);   // m rows (0..63)
            asm volatile("ld.shared.v2.b32 {%0,%1}, [%2];"
                         : "=r"(bf[nt][0]), "=r"(bf[nt][1])
                         : "r"(bs_ + (uint32_t)(nrow * ZROWB + s * 32 + (l & 3) * 8)));
        }
#pragma unroll
        for (int mt = 0; mt < 2; mt++) {
            uint32_t af[4];
            int mrow = wm * 32 + mt * 16 + (l >> 2);  // e rows (0..127)
            asm volatile("ld.shared.v2.b32 {%0,%1}, [%2];"
                         : "=r"(af[0]), "=r"(af[2])
                         : "r"(as_ + (uint32_t)(mrow * ZROWB + s * 32 + (l & 3) * 8)));
            asm volatile("ld.shared.v2.b32 {%0,%1}, [%2];"
                         : "=r"(af[1]), "=r"(af[3])
                         : "r"(as_ + (uint32_t)((mrow + 8) * ZROWB + s * 32 + (l & 3) * 8)));
#pragma unroll
            for (int nt = 0; nt < 2; nt++) {
                asm volatile(
                    "mma.sync.aligned.m16n8k16.row.col.f32.f16.f16.f32 "
                    "{%0,%1,%2,%3}, {%4,%5,%6,%7}, {%8,%9}, {%0,%1,%2,%3};"
                    : "+f"(c[mt][nt][0]), "+f"(c[mt][nt][1]),
                      "+f"(c[mt][nt][2]), "+f"(c[mt][nt][3])
                    : "r"(af[0]), "r"(af[1]), "r"(af[2]), "r"(af[3]),
                      "r"(bf[nt][0]), "r"(bf[nt][1]));
            }
        }
    }

    float2 dv[2];
#pragma unroll
    for (int nt = 0; nt < 2; nt++)
        dv[nt] = *(const float2*)&g_dinv[b * NN + m0g + wn * 16 + nt * 8 + 2 * (l & 3)];

    __syncthreads();   // all MMA reads of Wg region done; reuse as output buffer
#pragma unroll
    for (int mt = 0; mt < 2; mt++) {
        int e0 = wm * 32 + mt * 16 + (l >> 2);
#pragma unroll
        for (int nt = 0; nt < 2; nt++) {
            int mloc = wn * 16 + nt * 8 + 2 * (l & 3);
            int phys = (mloc & ~15) + kperm(mloc & 15);
            *(__half2*)(smc + ZA_OFF + (uint32_t)(e0 * ZROWB + phys * 2)) =
                __floats2half2_rn(c[mt][nt][0] * dv[nt].x, c[mt][nt][1] * dv[nt].y);
            *(__half2*)(smc + ZA_OFF + (uint32_t)((e0 + 8) * ZROWB + phys * 2)) =
                __floats2half2_rn(c[mt][nt][2] * dv[nt].x, c[mt][nt][3] * dv[nt].y);
        }
    }
    __syncthreads();

    // coalesced copy-out: 128 e-rows x 64 m-halves (128 B per row)
    __half* zTb = g_zT + (size_t)b * ND * NN;
#pragma unroll
    for (int it = 0; it < 2; it++) {
        int idx = it * 512 + t;
        int e = idx >> 3, ch = idx & 7;
        uint4 v = *(const uint4*)(smc + ZA_OFF + (uint32_t)(e * ZROWB + ch * 16));
        *(uint4*)(zTb + (size_t)e * NN + m0g + ch * 8) = v;
    }
}

// ---------------------------------------------------------------------------
// Kernel 4: fp16 m16n8k16 mma.sync GEMM — R9/R13 best config, unchanged.
// h[n,:] = tanh( dinv[n]*((dist+I)[n,:] @ z) + bg ) + h[n,:]  + fused stats.
// ---------------------------------------------------------------------------
__global__ void __launch_bounds__(256) k_gemm_mma(float* __restrict__ h,
                                                  const float* __restrict__ bg_l) {
    extern __shared__ char smc[];
    uint32_t sbase = smem_u32(smc);
    int t = threadIdx.x, l = t & 31, wid = t >> 5;
    int wm = wid & 1, wn = wid >> 1;
    int b = blockIdx.y, n0 = blockIdx.x * 128;
    const __half* Ab = g_dist + ((size_t)b * NN + n0) * NN;
    const __half* Bt = g_zT + (size_t)b * ND * NN;

    float c[4][4][4];
#pragma unroll
    for (int i = 0; i < 4; i++)
#pragma unroll
        for (int j = 0; j < 4; j++)
#pragma unroll
            for (int k = 0; k < 4; k++) c[i][j][k] = 0.f;

#define LOADT(P, K0)                                                             \
    {                                                                            \
        uint32_t xas = sbase + (P) * 40960u;                                     \
        uint32_t xbs = xas + 20480u;                                             \
        _Pragma("unroll")                                                        \
        for (int q = 0; q < 4; q++) {                                            \
            int idx = q * 256 + t;                                               \
            int r_ = idx >> 3;                                                   \
            int c16 = idx & 7;                                                   \
            uint32_t so = (uint32_t)(r_ * ROWB + c16 * 16);                      \
            asm volatile("cp.async.cg.shared.global [%0], [%1], 16;"             \
                         :: "r"(xas + so), "l"(Ab + (size_t)r_ * NN + (K0) + c16 * 8)); \
            asm volatile("cp.async.cg.shared.global [%0], [%1], 16;"             \
                         :: "r"(xbs + so), "l"(Bt + (size_t)r_ * NN + (K0) + c16 * 8)); \
        }                                                                        \
        asm volatile("cp.async.commit_group;");                                  \
    }

#define COMPUTE(P)                                                               \
    {                                                                            \
        uint32_t as_ = sbase + (P) * 40960u;                                     \
        uint32_t bs_ = as_ + 20480u;                                             \
        _Pragma("unroll")                                                        \
        for (int s = 0; s < 4; s++) {                                            \
            uint32_t bf[4][2];                                                   \
            _Pragma("unroll")                                                    \
            for (int nt = 0; nt < 4; nt++) {                                     \
                int nrow = wn * 32 + nt * 8 + (l >> 2);                          \
                asm volatile("ld.shared.v2.b32 {%0,%1}, [%2];"                   \
                             : "=r"(bf[nt][0]), "=r"(bf[nt][1])                  \
                             : "r"(bs_ + (uint32_t)(nrow * ROWB + s * 32 + (l & 3) * 8))); \
            }                                                                    \
            _Pragma("unroll")                                                    \
            for (int mt = 0; mt < 4; mt++) {                                     \
                uint32_t af[4];                                                  \
                int mrow = wm * 64 + mt * 16 + (l >> 2);                         \
                asm volatile("ld.shared.v2.b32 {%0,%1}, [%2];"                   \
                             : "=r"(af[0]), "=r"(af[2])                          \
                             : "r"(as_ + (uint32_t)(mrow * ROWB + s * 32 + (l & 3) * 8))); \
                asm volatile("ld.shared.v2.b32 {%0,%1}, [%2];"                   \
                             : "=r"(af[1]), "=r"(af[3])                          \
                             : "r"(as_ + (uint32_t)((mrow + 8) * ROWB + s * 32 + (l & 3) * 8))); \
                _Pragma("unroll")                                                \
                for (int nt = 0; nt < 4; nt++) {                                 \
                    asm volatile(                                                \
                        "mma.sync.aligned.m16n8k16.row.col.f32.f16.f16.f32 "     \
                        "{%0,%1,%2,%3}, {%4,%5,%6,%7}, {%8,%9}, {%0,%1,%2,%3};"  \
                        : "+f"(c[mt][nt][0]), "+f"(c[mt][nt][1]),                \
                          "+f"(c[mt][nt][2]), "+f"(c[mt][nt][3])                 \
                        : "r"(af[0]), "r"(af[1]), "r"(af[2]), "r"(af[3]),        \
                          "r"(bf[nt][0]), "r"(bf[nt][1]));                       \
                }                                                                \
            }                                                                    \
        }                                                                        \
    }

    LOADT(0, 0);
    LOADT(1, BK);
    int p = 0;
    for (int it = 0; it < NIT; it++) {
        if (it + 1 < NIT)
            asm volatile("cp.async.wait_group 1;");
        else
            asm volatile("cp.async.wait_group 0;");
        __syncthreads();
        if (it + 2 < NIT) {
            int pn = (it + 2) % 3;
            LOADT(pn, (it + 2) * BK);
        }
        COMPUTE(p);
        p = (p + 1) % 3;
    }

    // epilogue: dinv + bias + tanh + residual, accumulating stats partials
    float ssum[8], ssq[8];
#pragma unroll
    for (int j = 0; j < 8; j++) { ssum[j] = 0.f; ssq[j] = 0.f; }
#pragma unroll
    for (int mt = 0; mt < 4; mt++) {
        int r0 = n0 + wm * 64 + mt * 16 + (l >> 2);
        int r1 = r0 + 8;
        float dv0 = g_dinv[b * NN + r0];
        float dv1 = g_dinv[b * NN + r1];
#pragma unroll
        for (int nt = 0; nt < 4; nt++) {
            int cc = wn * 32 + nt * 8 + 2 * (l & 3);
            float bg0 = bg_l[cc], bg1 = bg_l[cc + 1];
            size_t h0o = ((size_t)b * NN + r0) * ND + cc;
            size_t h1o = ((size_t)b * NN + r1) * ND + cc;
            float2 hv0 = *(const float2*)&h[h0o];
            float2 hv1 = *(const float2*)&h[h1o];
            float2 o0, o1;
            o0.x = tanhf(dv0 * c[mt][nt][0] + bg0) + hv0.x;
            o0.y = tanhf(dv0 * c[mt][nt][1] + bg1) + hv0.y;
            o1.x = tanhf(dv1 * c[mt][nt][2] + bg0) + hv1.x;
            o1.y = tanhf(dv1 * c[mt][nt][3] + bg1) + hv1.y;
            *(float2*)&h[h0o] = o0;
            *(float2*)&h[h1o] = o1;
            ssum[2 * nt]     += o0.x + o1.x;
            ssum[2 * nt + 1] += o0.y + o1.y;
            ssq[2 * nt]      += o0.x * o0.x + o1.x * o1.x;
            ssq[2 * nt + 1]  += o0.y * o0.y + o1.y * o1.y;
        }
    }
#pragma unroll
    for (int off = 4; off < 32; off <<= 1)
#pragma unroll
        for (int j = 0; j < 8; j++) {
            ssum[j] += __shfl_xor_sync(0xffffffffu, ssum[j], off);
            ssq[j]  += __shfl_xor_sync(0xffffffffu, ssq[j], off);
        }
    __syncthreads();           // mainloop smem dead; reuse for cross-warp stats
    float* sp = (float*)smc;   // [0:256) sums (wm-major), [256:512) sumsqs
    if ((l >> 2) == 0) {
#pragma unroll
        for (int j = 0; j < 8; j++) {
            int col = wn * 32 + (j >> 1) * 8 + 2 * (l & 3) + (j & 1);
            sp[wm * 128 + col] = ssum[j];
            sp[256 + wm * 128 + col] = ssq[j];
        }
    }
    __syncthreads();
    if (t < 128) {
        float s = sp[t] + sp[128 + t];
        float q = sp[256 + t] + sp[384 + t];
        g_part[((size_t)b * NTILES + blockIdx.x) * ND + t] = make_float2(s, q);
    }
#undef LOADT
#undef COMPUTE
}

// ---------------------------------------------------------------------------
// Kernel 5: finalize GraphNorm stats (final layer only)
// ---------------------------------------------------------------------------
__global__ void k_fin(const float* __restrict__ gna) {
    int b = blockIdx.x, d = threadIdx.x;
    float s = 0.f, q = 0.f;
#pragma unroll
    for (int tile = 0; tile < NTILES; tile++) {
        float2 v = g_part[((size_t)b * NTILES + tile) * ND + d];
        s += v.x; q += v.y;
    }
    float mean = s * (1.f / NN);
    float eh2 = q * (1.f / NN);
    float a = gna[d];
    float var = eh2 - (2.f * a - a * a) * mean * mean;
    g_mean[b * ND + d] = mean;
    g_rstd[b * ND + d] = rsqrtf(var + 1e-5f);
}

// ---------------------------------------------------------------------------
// Kernel 6: normalize in place (final layer only)
// ---------------------------------------------------------------------------
__global__ void k_norm(float* __restrict__ h, const float* __restrict__ gnw,
                       const float* __restrict__ gnb, const float* __restrict__ gna) {
    int idx = blockIdx.x * 256 + threadIdx.x;
    int d = idx & (ND - 1);
    int b = idx >> 18;
    float m = g_mean[b * ND + d];
    float rs = g_rstd[b * ND + d];
    float v = h[idx];
    h[idx] = gnw[d] * (v - gna[d] * m) * rs + gnb[d];
}

// ---------------------------------------------------------------------------
extern "C" void kernel_launch(void* const* d_in, const int* in_sizes, int n_in,
                              void* d_out, int out_size) {
    const float* inst = (const float*)d_in[0];
    const float* Wn   = (const float*)d_in[1];
    const float* bn   = (const float*)d_in[2];
    const float* Wg   = (const float*)d_in[3];
    const float* bg   = (const float*)d_in[4];
    const float* gnw  = (const float*)d_in[5];
    const float* gnb  = (const float*)d_in[6];
    const float* gna  = (const float*)d_in[7];
    float* h = (float*)d_out;

    const int SMEM_GEMM = 3 * 40960;   // 3 stages x (A 20KB + B 20KB)
    const int SMEM_Z    = (int)ZSMEM;  // 56320
    static int smem_set = 0;
    if (!smem_set) {
        cudaFuncSetAttribute(k_gemm_mma, cudaFuncAttributeMaxDynamicSharedMemorySize, SMEM_GEMM);
        cudaFuncSetAttribute(k_z, cudaFuncAttributeMaxDynamicSharedMemorySize, SMEM_Z);
        smem_set = 1;
    }

    k_dist<<<dim3(NN, NB), 256>>>(inst);
    for (int l = 0; l < 3; l++) {
        k_z<<<NB * NN / 64, 512, SMEM_Z>>>(h, Wg + l * ND * ND,
                                           l == 0 ? 0 : 1, gnw, gnb, gna,
                                           inst, Wn, bn);
        k_gemm_mma<<<dim3(NTILES, NB), 256, SMEM_GEMM>>>(h, bg + l * ND);
    }
    k_fin<<<NB, ND>>>(gna);
    k_norm<<<(NB * NN * ND) / 256, 256>>>(h, gnw, gnb, gna);
}

// round 16
// speedup vs baseline: 1.4427x; 1.0293x over previous
#include <cuda_runtime.h>
#include <cuda_fp16.h>
#include <math.h>
#include <stdint.h>

#define NB 8
#define NN 2048
#define ND 128
#define BK 64
#define NIT (NN / BK)   // 32 k-chunks
#define ROWB 160u       // gemm smem row stride bytes (80 halves) -> conflict-free LDS.64
#define ZROWB 288u      // k_z smem row stride bytes: 72 mod 32 = 8, conflict-free pattern
#define NTILES 16       // gemm M-tiles per batch (128 rows each)
// k_z smem layout: Wg 128 rows, h 128 rows, stats arrays
#define ZA_OFF 0u
#define ZB_OFF (128u * ZROWB)             // 36864
#define ZST_OFF (ZB_OFF + 128u * ZROWB)   // 73728
#define ZSMEM (ZST_OFF + 1024u)           // 74752

// ---- scratch (__device__ globals: allocation-guard safe) ----
__device__ __half g_dist[(size_t)NB * NN * NN];   // 67 MB, k-pair-permuted, diag has +1
__device__ float  g_dinv[NB * NN];
__device__ __half g_zT[(size_t)NB * ND * NN];     // [b][d][m], permuted in m
__device__ float  g_mean[NB * ND];
__device__ float  g_rstd[NB * ND];
__device__ float2 g_part[NB * NTILES * ND];       // per-(b, n-tile) stats partials

__device__ __forceinline__ uint32_t smem_u32(const void* p) {
    uint32_t a;
    asm("{ .reg .u64 t; cvta.to.shared.u64 t, %1; cvt.u32.u64 %0, t; }" : "=r"(a) : "l"(p));
    return a;
}

// logical k within 16-block -> physical position (pair permutation so that an
// LDS.64 at 4q yields logical pairs {2q,2q+1} and {2q+8,2q+9})
__device__ __forceinline__ int kperm(int w) {
    return 4 * ((w & 7) >> 1) + ((w >> 3) << 1) + (w & 1);
}

// FMA-only sqrt: bit-trick rsqrt + 2 Newton iterations (~4e-6 rel err, far
// below the fp16 storage rounding of 5e-4). Avoids the MUFU throughput wall.
__device__ __forceinline__ float fast_sqrt(float x) {
    float xh = 0.5f * x;
    float y = __int_as_float(0x5f3759df - (__float_as_int(x) >> 1));
    y = y * (1.5f - xh * y * y);
    y = y * (1.5f - xh * y * y);
    return x * y;
}

// ---------------------------------------------------------------------------
// Kernel 1: dist rows (fp16, permuted, +1 diag) + degree -> dinv
// v3: coords staged in skewed smem (conflict-free), each thread computes one
// permuted half-block in registers -> ONE STG.128 (8x fewer store instrs).
// Inverse perm: physical pb -> logical w = 8*((pb>>1)&1) + 2*(pb>>2) + (pb&1).
// ---------------------------------------------------------------------------
__global__ void k_dist(const float* __restrict__ inst) {
    __shared__ float2 sx[NN + NN / 16];   // skew: index m + (m>>4)
    __shared__ float red[256];
    int n = blockIdx.x, b = blockIdx.y;
    int t = threadIdx.x;
    const float2* xb = (const float2*)(inst + (size_t)b * NN * 2);
#pragma unroll
    for (int q = 0; q < 8; q++) {
        int m = q * 256 + t;
        sx[m + (m >> 4)] = xb[m];
    }
    __syncthreads();
    float2 xn = sx[n + (n >> 4)];
    float sqn = xn.x * xn.x + xn.y * xn.y;
    __half* drow = g_dist + (size_t)(b * NN + n) * NN;
    int block = t >> 1, half = t & 1;
    int mbase = block * 16;
    float acc = 0.f;
    uint32_t ov[4];
#pragma unroll
    for (int pp = 0; pp < 4; pp++) {
        float dval[2];
#pragma unroll
        for (int cc = 0; cc < 2; cc++) {
            int pb = 8 * half + 2 * pp + cc;
            int w = 8 * ((pb >> 1) & 1) + 2 * (pb >> 2) + (pb & 1);
            int m = mbase + w;
            float2 xm = sx[m + (m >> 4)];
            float sqm = xm.x * xm.x + xm.y * xm.y;
            float dot = xn.x * xm.x + xn.y * xm.y;
            float d2 = sqn + sqm - 2.f * dot;
            float d = (d2 > 0.f) ? fast_sqrt(d2) : 0.f;
            acc += d;
            dval[cc] = (m == n) ? d + 1.0f : d;   // self-loop on diagonal
        }
        __half2 hh = __floats2half2_rn(dval[0], dval[1]);
        ov[pp] = *(uint32_t*)&hh;
    }
    *(uint4*)(drow + mbase + 8 * half) = make_uint4(ov[0], ov[1], ov[2], ov[3]);

    red[t] = acc;
    __syncthreads();
    for (int s = 128; s > 0; s >>= 1) {
        if (t < s) red[t] += red[t + s];
        __syncthreads();
    }
    if (t == 0)
        g_dinv[b * NN + n] = rsqrtf(1.0f + red[0]);
}

// ---------------------------------------------------------------------------
// Kernel 3 (fp16 MMA, output-major, 128-row m-tiles, grid 128, 512 threads):
//   zT[b][e][m] = dinv[m] * sum_d Wg[e,d] * hn[m,d]
// Register-batched staging (16 float4 loads in flight per thread); Wg staged
// once per 128 m-rows (half the fixed cost of the 64-row version).
// mode 0: h = inst@Wn^T+bn during staging; mode 1: inline stats finalize +
// GraphNorm applied during staging, normalized h written back.
// ---------------------------------------------------------------------------
__global__ void __launch_bounds__(512) k_z(float* __restrict__ h,
                                           const float* __restrict__ Wg,
                                           int mode,
                                           const float* __restrict__ gnw,
                                           const float* __restrict__ gnb,
                                           const float* __restrict__ gna,
                                           const float* __restrict__ inst,
                                           const float* __restrict__ Wn,
                                           const float* __restrict__ bn) {
    extern __shared__ char smc[];
    uint32_t sbase = smem_u32(smc);
    uint32_t as_ = sbase + ZA_OFF, bs_ = sbase + ZB_OFF;
    float* smean = (float*)(smc + ZST_OFF);
    float* srstd = (float*)(smc + ZST_OFF + 512);
    int t = threadIdx.x, l = t & 31, wid = t >> 5;
    int wm = wid & 3, wn = wid >> 2;   // wm: e-quarter (32 rows), wn: m-quarter (32 cols)
    int row0 = blockIdx.x * 128;       // global row over NB*NN (m dimension)
    int b = row0 >> 11;
    int m0g = row0 & (NN - 1);

    if (mode == 1) {
        if (t < 128) {
            float s = 0.f, q = 0.f;
#pragma unroll
            for (int tile = 0; tile < NTILES; tile++) {
                float2 v = g_part[((size_t)b * NTILES + tile) * ND + t];
                s += v.x; q += v.y;
            }
            float mean = s * (1.f / NN);
            float eh2 = q * (1.f / NN);
            float a = gna[t];
            float var = eh2 - (2.f * a - a * a) * mean * mean;
            smean[t] = mean;
            srstd[t] = rsqrtf(var + 1e-5f);
        }
        __syncthreads();
    }

    // ---- phase 1: batched gmem loads into registers (MLP = 16/thread) ----
    float4 wbuf[8];   // Wg: 128 rows x 32 float4 = 4096 / 512 thr
    float4 hbuf[8];   // h:  128 rows x 32 float4 = 4096 / 512 thr
#pragma unroll
    for (int q = 0; q < 8; q++) {
        int idx = q * 512 + t;
        wbuf[q] = *(const float4*)&Wg[(idx >> 5) * ND + 4 * (idx & 31)];
    }
    if (mode == 0) {
#pragma unroll
        for (int q = 0; q < 8; q++) {
            int idx = q * 512 + t;
            int grow = row0 + (idx >> 5), u = idx & 31;
            float2 x = ((const float2*)inst)[grow];
#pragma unroll
            for (int j = 0; j < 4; j++) {
                int d = 4 * u + j;
                ((float*)&hbuf[q])[j] = x.x * Wn[2 * d] + x.y * Wn[2 * d + 1] + bn[d];
            }
        }
    } else {
#pragma unroll
        for (int q = 0; q < 8; q++) {
            int idx = q * 512 + t;
            hbuf[q] = *(const float4*)&h[(size_t)(row0 + (idx >> 5)) * ND + 4 * (idx & 31)];
        }
    }

    // ---- phase 2: convert + permuted smem stores (and h writeback) ----
#pragma unroll
    for (int q = 0; q < 8; q++) {
        int idx = q * 512 + t;
        int r = idx >> 5, u = idx & 31;
        int blk = u >> 2;
        int p0 = 2 * (u & 3), p1 = p0 + 1;
        int s0 = (p0 < 4) ? 2 * p0 : 2 * (p0 - 4) + 1;
        int s1 = (p1 < 4) ? 2 * p1 : 2 * (p1 - 4) + 1;
        uint32_t base = (uint32_t)(r * ZROWB + blk * 32);
        *(__half2*)(smc + ZA_OFF + base + s0 * 4) = __floats2half2_rn(wbuf[q].x, wbuf[q].y);
        *(__half2*)(smc + ZA_OFF + base + s1 * 4) = __floats2half2_rn(wbuf[q].z, wbuf[q].w);
    }
#pragma unroll
    for (int q = 0; q < 8; q++) {
        int idx = q * 512 + t;
        int r = idx >> 5, u = idx & 31;
        int grow = row0 + r;
        float4 hv = hbuf[q];
        if (mode == 1) {
            float4 mw = *(const float4*)&smean[4 * u];
            float4 rw = *(const float4*)&srstd[4 * u];
            float4 w_ = *(const float4*)&gnw[4 * u];
            float4 b_ = *(const float4*)&gnb[4 * u];
            float4 a_ = *(const float4*)&gna[4 * u];
            hv.x = w_.x * (hv.x - a_.x * mw.x) * rw.x + b_.x;
            hv.y = w_.y * (hv.y - a_.y * mw.y) * rw.y + b_.y;
            hv.z = w_.z * (hv.z - a_.z * mw.z) * rw.z + b_.z;
            hv.w = w_.w * (hv.w - a_.w * mw.w) * rw.w + b_.w;
        }
        *(float4*)&h[(size_t)grow * ND + 4 * u] = hv;
        int blk = u >> 2;
        int p0 = 2 * (u & 3), p1 = p0 + 1;
        int s0 = (p0 < 4) ? 2 * p0 : 2 * (p0 - 4) + 1;
        int s1 = (p1 < 4) ? 2 * p1 : 2 * (p1 - 4) + 1;
        uint32_t base = (uint32_t)(r * ZROWB + blk * 32);
        *(__half2*)(smc + ZB_OFF + base + s0 * 4) = __floats2half2_rn(hv.x, hv.y);
        *(__half2*)(smc + ZB_OFF + base + s1 * 4) = __floats2half2_rn(hv.z, hv.w);
    }
    __syncthreads();

    // ---- MMA: output e x m = 128 x 128; 16 warps (4x4), warp tile 32e x 32m
    float c[2][4][4];
#pragma unroll
    for (int i = 0; i < 2; i++)
#pragma unroll
        for (int j = 0; j < 4; j++)
#pragma unroll
            for (int k = 0; k < 4; k++) c[i][j][k] = 0.f;

#pragma unroll
    for (int s = 0; s < 8; s++) {
        uint32_t bf[4][2];
#pragma unroll
        for (int nt = 0; nt < 4; nt++) {
            int nrow = wn * 32 + nt * 8 + (l >> 2);   // m rows (0..127)
            asm volatile("ld.shared.v2.b32 {%0,%1}, [%2];"
                         : "=r"(bf[nt][0]), "=r"(bf[nt][1])
                         : "r"(bs_ + (uint32_t)(nrow * ZROWB + s * 32 + (l & 3) * 8)));
        }
#pragma unroll
        for (int mt = 0; mt < 2; mt++) {
            uint32_t af[4];
            int mrow = wm * 32 + mt * 16 + (l >> 2);  // e rows (0..127)
            asm volatile("ld.shared.v2.b32 {%0,%1}, [%2];"
                         : "=r"(af[0]), "=r"(af[2])
                         : "r"(as_ + (uint32_t)(mrow * ZROWB + s * 32 + (l & 3) * 8)));
            asm volatile("ld.shared.v2.b32 {%0,%1}, [%2];"
                         : "=r"(af[1]), "=r"(af[3])
                         : "r"(as_ + (uint32_t)((mrow + 8) * ZROWB + s * 32 + (l & 3) * 8)));
#pragma unroll
            for (int nt = 0; nt < 4; nt++) {
                asm volatile(
                    "mma.sync.aligned.m16n8k16.row.col.f32.f16.f16.f32 "
                    "{%0,%1,%2,%3}, {%4,%5,%6,%7}, {%8,%9}, {%0,%1,%2,%3};"
                    : "+f"(c[mt][nt][0]), "+f"(c[mt][nt][1]),
                      "+f"(c[mt][nt][2]), "+f"(c[mt][nt][3])
                    : "r"(af[0]), "r"(af[1]), "r"(af[2]), "r"(af[3]),
                      "r"(bf[nt][0]), "r"(bf[nt][1]));
            }
        }
    }

    float2 dv[4];
#pragma unroll
    for (int nt = 0; nt < 4; nt++)
        dv[nt] = *(const float2*)&g_dinv[b * NN + m0g + wn * 32 + nt * 8 + 2 * (l & 3)];

    __syncthreads();   // all MMA reads of Wg region done; reuse as output buffer
#pragma unroll
    for (int mt = 0; mt < 2; mt++) {
        int e0 = wm * 32 + mt * 16 + (l >> 2);
#pragma unroll
        for (int nt = 0; nt < 4; nt++) {
            int mloc = wn * 32 + nt * 8 + 2 * (l & 3);
            int phys = (mloc & ~15) + kperm(mloc & 15);
            *(__half2*)(smc + ZA_OFF + (uint32_t)(e0 * ZROWB + phys * 2)) =
                __floats2half2_rn(c[mt][nt][0] * dv[nt].x, c[mt][nt][1] * dv[nt].y);
            *(__half2*)(smc + ZA_OFF + (uint32_t)((e0 + 8) * ZROWB + phys * 2)) =
                __floats2half2_rn(c[mt][nt][2] * dv[nt].x, c[mt][nt][3] * dv[nt].y);
        }
    }
    __syncthreads();

    // coalesced copy-out: 128 e-rows x 128 m-halves (256 B per row)
    __half* zTb = g_zT + (size_t)b * ND * NN;
#pragma unroll
    for (int it = 0; it < 4; it++) {
        int idx = it * 512 + t;
        int e = idx >> 4, ch = idx & 15;
        uint4 v = *(const uint4*)(smc + ZA_OFF + (uint32_t)(e * ZROWB + ch * 16));
        *(uint4*)(zTb + (size_t)e * NN + m0g + ch * 8) = v;
    }
}

// ---------------------------------------------------------------------------
// Kernel 4: fp16 m16n8k16 mma.sync GEMM — R9/R13 best config, unchanged.
// h[n,:] = tanh( dinv[n]*((dist+I)[n,:] @ z) + bg ) + h[n,:]  + fused stats.
// ---------------------------------------------------------------------------
__global__ void __launch_bounds__(256) k_gemm_mma(float* __restrict__ h,
                                                  const float* __restrict__ bg_l) {
    extern __shared__ char smc[];
    uint32_t sbase = smem_u32(smc);
    int t = threadIdx.x, l = t & 31, wid = t >> 5;
    int wm = wid & 1, wn = wid >> 1;
    int b = blockIdx.y, n0 = blockIdx.x * 128;
    const __half* Ab = g_dist + ((size_t)b * NN + n0) * NN;
    const __half* Bt = g_zT + (size_t)b * ND * NN;

    float c[4][4][4];
#pragma unroll
    for (int i = 0; i < 4; i++)
#pragma unroll
        for (int j = 0; j < 4; j++)
#pragma unroll
            for (int k = 0; k < 4; k++) c[i][j][k] = 0.f;

#define LOADT(P, K0)                                                             \
    {                                                                            \
        uint32_t xas = sbase + (P) * 40960u;                                     \
        uint32_t xbs = xas + 20480u;                                             \
        _Pragma("unroll")                                                        \
        for (int q = 0; q < 4; q++) {                                            \
            int idx = q * 256 + t;                                               \
            int r_ = idx >> 3;                                                   \
            int c16 = idx & 7;                                                   \
            uint32_t so = (uint32_t)(r_ * ROWB + c16 * 16);                      \
            asm volatile("cp.async.cg.shared.global [%0], [%1], 16;"             \
                         :: "r"(xas + so), "l"(Ab + (size_t)r_ * NN + (K0) + c16 * 8)); \
            asm volatile("cp.async.cg.shared.global [%0], [%1], 16;"             \
                         :: "r"(xbs + so), "l"(Bt + (size_t)r_ * NN + (K0) + c16 * 8)); \
        }                                                                        \
        asm volatile("cp.async.commit_group;");                                  \
    }

#define COMPUTE(P)                                                               \
    {                                                                            \
        uint32_t as_ = sbase + (P) * 40960u;                                     \
        uint32_t bs_ = as_ + 20480u;                                             \
        _Pragma("unroll")                                                        \
        for (int s = 0; s < 4; s++) {                                            \
            uint32_t bf[4][2];                                                   \
            _Pragma("unroll")                                                    \
            for (int nt = 0; nt < 4; nt++) {                                     \
                int nrow = wn * 32 + nt * 8 + (l >> 2);                          \
                asm volatile("ld.shared.v2.b32 {%0,%1}, [%2];"                   \
                             : "=r"(bf[nt][0]), "=r"(bf[nt][1])                  \
                             : "r"(bs_ + (uint32_t)(nrow * ROWB + s * 32 + (l & 3) * 8))); \
            }                                                                    \
            _Pragma("unroll")                                                    \
            for (int mt = 0; mt < 4; mt++) {                                     \
                uint32_t af[4];                                                  \
                int mrow = wm * 64 + mt * 16 + (l >> 2);                         \
                asm volatile("ld.shared.v2.b32 {%0,%1}, [%2];"                   \
                             : "=r"(af[0]), "=r"(af[2])                          \
                             : "r"(as_ + (uint32_t)(mrow * ROWB + s * 32 + (l & 3) * 8))); \
                asm volatile("ld.shared.v2.b32 {%0,%1}, [%2];"                   \
                             : "=r"(af[1]), "=r"(af[3])                          \
                             : "r"(as_ + (uint32_t)((mrow + 8) * ROWB + s * 32 + (l & 3) * 8))); \
                _Pragma("unroll")                                                \
                for (int nt = 0; nt < 4; nt++) {                                 \
                    asm volatile(                                                \
                        "mma.sync.aligned.m16n8k16.row.col.f32.f16.f16.f32 "     \
                        "{%0,%1,%2,%3}, {%4,%5,%6,%7}, {%8,%9}, {%0,%1,%2,%3};"  \
                        : "+f"(c[mt][nt][0]), "+f"(c[mt][nt][1]),                \
                          "+f"(c[mt][nt][2]), "+f"(c[mt][nt][3])                 \
                        : "r"(af[0]), "r"(af[1]), "r"(af[2]), "r"(af[3]),        \
                          "r"(bf[nt][0]), "r"(bf[nt][1]));                       \
                }                                                                \
            }                                                                    \
        }                                                                        \
    }

    LOADT(0, 0);
    LOADT(1, BK);
    int p = 0;
    for (int it = 0; it < NIT; it++) {
        if (it + 1 < NIT)
            asm volatile("cp.async.wait_group 1;");
        else
            asm volatile("cp.async.wait_group 0;");
        __syncthreads();
        if (it + 2 < NIT) {
            int pn = (it + 2) % 3;
            LOADT(pn, (it + 2) * BK);
        }
        COMPUTE(p);
        p = (p + 1) % 3;
    }

    // epilogue: dinv + bias + tanh + residual, accumulating stats partials
    float ssum[8], ssq[8];
#pragma unroll
    for (int j = 0; j < 8; j++) { ssum[j] = 0.f; ssq[j] = 0.f; }
#pragma unroll
    for (int mt = 0; mt < 4; mt++) {
        int r0 = n0 + wm * 64 + mt * 16 + (l >> 2);
        int r1 = r0 + 8;
        float dv0 = g_dinv[b * NN + r0];
        float dv1 = g_dinv[b * NN + r1];
#pragma unroll
        for (int nt = 0; nt < 4; nt++) {
            int cc = wn * 32 + nt * 8 + 2 * (l & 3);
            float bg0 = bg_l[cc], bg1 = bg_l[cc + 1];
            size_t h0o = ((size_t)b * NN + r0) * ND + cc;
            size_t h1o = ((size_t)b * NN + r1) * ND + cc;
            float2 hv0 = *(const float2*)&h[h0o];
            float2 hv1 = *(const float2*)&h[h1o];
            float2 o0, o1;
            o0.x = tanhf(dv0 * c[mt][nt][0] + bg0) + hv0.x;
            o0.y = tanhf(dv0 * c[mt][nt][1] + bg1) + hv0.y;
            o1.x = tanhf(dv1 * c[mt][nt][2] + bg0) + hv1.x;
            o1.y = tanhf(dv1 * c[mt][nt][3] + bg1) + hv1.y;
            *(float2*)&h[h0o] = o0;
            *(float2*)&h[h1o] = o1;
            ssum[2 * nt]     += o0.x + o1.x;
            ssum[2 * nt + 1] += o0.y + o1.y;
            ssq[2 * nt]      += o0.x * o0.x + o1.x * o1.x;
            ssq[2 * nt + 1]  += o0.y * o0.y + o1.y * o1.y;
        }
    }
#pragma unroll
    for (int off = 4; off < 32; off <<= 1)
#pragma unroll
        for (int j = 0; j < 8; j++) {
            ssum[j] += __shfl_xor_sync(0xffffffffu, ssum[j], off);
            ssq[j]  += __shfl_xor_sync(0xffffffffu, ssq[j], off);
        }
    __syncthreads();           // mainloop smem dead; reuse for cross-warp stats
    float* sp = (float*)smc;   // [0:256) sums (wm-major), [256:512) sumsqs
    if ((l >> 2) == 0) {
#pragma unroll
        for (int j = 0; j < 8; j++) {
            int col = wn * 32 + (j >> 1) * 8 + 2 * (l & 3) + (j & 1);
            sp[wm * 128 + col] = ssum[j];
            sp[256 + wm * 128 + col] = ssq[j];
        }
    }
    __syncthreads();
    if (t < 128) {
        float s = sp[t] + sp[128 + t];
        float q = sp[256 + t] + sp[384 + t];
        g_part[((size_t)b * NTILES + blockIdx.x) * ND + t] = make_float2(s, q);
    }
#undef LOADT
#undef COMPUTE
}

// ---------------------------------------------------------------------------
// Kernel 5: finalize GraphNorm stats (final layer only)
// ---------------------------------------------------------------------------
__global__ void k_fin(const float* __restrict__ gna) {
    int b = blockIdx.x, d = threadIdx.x;
    float s = 0.f, q = 0.f;
#pragma unroll
    for (int tile = 0; tile < NTILES; tile++) {
        float2 v = g_part[((size_t)b * NTILES + tile) * ND + d];
        s += v.x; q += v.y;
    }
    float mean = s * (1.f / NN);
    float eh2 = q * (1.f / NN);
    float a = gna[d];
    float var = eh2 - (2.f * a - a * a) * mean * mean;
    g_mean[b * ND + d] = mean;
    g_rstd[b * ND + d] = rsqrtf(var + 1e-5f);
}

// ---------------------------------------------------------------------------
// Kernel 6: normalize in place (final layer only)
// ---------------------------------------------------------------------------
__global__ void k_norm(float* __restrict__ h, const float* __restrict__ gnw,
                       const float* __restrict__ gnb, const float* __restrict__ gna) {
    int idx = blockIdx.x * 256 + threadIdx.x;
    int d = idx & (ND - 1);
    int b = idx >> 18;
    float m = g_mean[b * ND + d];
    float rs = g_rstd[b * ND + d];
    float v = h[idx];
    h[idx] = gnw[d] * (v - gna[d] * m) * rs + gnb[d];
}

// ---------------------------------------------------------------------------
extern "C" void kernel_launch(void* const* d_in, const int* in_sizes, int n_in,
                              void* d_out, int out_size) {
    const float* inst = (const float*)d_in[0];
    const float* Wn   = (const float*)d_in[1];
    const float* bn   = (const float*)d_in[2];
    const float* Wg   = (const float*)d_in[3];
    const float* bg   = (const float*)d_in[4];
    const float* gnw  = (const float*)d_in[5];
    const float* gnb  = (const float*)d_in[6];
    const float* gna  = (const float*)d_in[7];
    float* h = (float*)d_out;

    const int SMEM_GEMM = 3 * 40960;   // 3 stages x (A 20KB + B 20KB)
    const int SMEM_Z    = (int)ZSMEM;  // 74752
    static int smem_set = 0;
    if (!smem_set) {
        cudaFuncSetAttribute(k_gemm_mma, cudaFuncAttributeMaxDynamicSharedMemorySize, SMEM_GEMM);
        cudaFuncSetAttribute(k_z, cudaFuncAttributeMaxDynamicSharedMemorySize, SMEM_Z);
        smem_set = 1;
    }

    k_dist<<<dim3(NN, NB), 256>>>(inst);
    for (int l = 0; l < 3; l++) {
        k_z<<<NB * NN / 128, 512, SMEM_Z>>>(h, Wg + l * ND * ND,
                                            l == 0 ? 0 : 1, gnw, gnb, gna,
                                            inst, Wn, bn);
        k_gemm_mma<<<dim3(NTILES, NB), 256, SMEM_GEMM>>>(h, bg + l * ND);
    }
    k_fin<<<NB, ND>>>(gna);
    k_norm<<<(NB * NN * ND) / 256, 256>>>(h, gnw, gnb, gna);
}

// round 17
// speedup vs baseline: 1.5460x; 1.0716x over previous
#include <cuda_runtime.h>
#include <cuda_fp16.h>
#include <math.h>
#include <stdint.h>

#define NB 8
#define NN 2048
#define ND 128
#define BK 128
#define NIT (NN / BK)   // 16 k-chunks
#define ROWB 288u       // gemm smem row stride bytes (BK=128): 72 words ≡ 8 mod 32 -> conflict-free
#define STAGEB (2u * 128u * ROWB)   // 73728 per stage (A + B)
#define ZROWB 288u      // k_z smem row stride bytes (same pattern)
#define NTILES 16       // gemm M-tiles per batch (128 rows each)
// k_z smem layout: Wg 128 rows, h 128 rows, stats arrays
#define ZA_OFF 0u
#define ZB_OFF (128u * ZROWB)             // 36864
#define ZST_OFF (ZB_OFF + 128u * ZROWB)   // 73728
#define ZSMEM (ZST_OFF + 1024u)           // 74752

// ---- scratch (__device__ globals: allocation-guard safe) ----
__device__ __half g_dist[(size_t)NB * NN * NN];   // 67 MB, k-pair-permuted, diag has +1
__device__ float  g_dinv[NB * NN];
__device__ __half g_zT[(size_t)NB * ND * NN];     // [b][d][m], permuted in m
__device__ float2 g_part[NB * NTILES * ND];       // per-(b, n-tile) stats partials

__device__ __forceinline__ uint32_t smem_u32(const void* p) {
    uint32_t a;
    asm("{ .reg .u64 t; cvta.to.shared.u64 t, %1; cvt.u32.u64 %0, t; }" : "=r"(a) : "l"(p));
    return a;
}

// logical k within 16-block -> physical position (pair permutation so that an
// LDS.64 at 4q yields logical pairs {2q,2q+1} and {2q+8,2q+9})
__device__ __forceinline__ int kperm(int w) {
    return 4 * ((w & 7) >> 1) + ((w >> 3) << 1) + (w & 1);
}

// FMA-only sqrt: bit-trick rsqrt + 2 Newton iterations (~4e-6 rel err, far
// below the fp16 storage rounding of 5e-4). Avoids the MUFU throughput wall.
__device__ __forceinline__ float fast_sqrt(float x) {
    float xh = 0.5f * x;
    float y = __int_as_float(0x5f3759df - (__float_as_int(x) >> 1));
    y = y * (1.5f - xh * y * y);
    y = y * (1.5f - xh * y * y);
    return x * y;
}

// ---------------------------------------------------------------------------
// Kernel 1: dist rows (fp16, permuted, +1 diag) + degree -> dinv
// coords staged in skewed smem; one STG.128 per thread-half-block.
// ---------------------------------------------------------------------------
__global__ void k_dist(const float* __restrict__ inst) {
    __shared__ float2 sx[NN + NN / 16];   // skew: index m + (m>>4)
    __shared__ float red[256];
    int n = blockIdx.x, b = blockIdx.y;
    int t = threadIdx.x;
    const float2* xb = (const float2*)(inst + (size_t)b * NN * 2);
#pragma unroll
    for (int q = 0; q < 8; q++) {
        int m = q * 256 + t;
        sx[m + (m >> 4)] = xb[m];
    }
    __syncthreads();
    float2 xn = sx[n + (n >> 4)];
    float sqn = xn.x * xn.x + xn.y * xn.y;
    __half* drow = g_dist + (size_t)(b * NN + n) * NN;
    int block = t >> 1, half = t & 1;
    int mbase = block * 16;
    float acc = 0.f;
    uint32_t ov[4];
#pragma unroll
    for (int pp = 0; pp < 4; pp++) {
        float dval[2];
#pragma unroll
        for (int cc = 0; cc < 2; cc++) {
            int pb = 8 * half + 2 * pp + cc;
            int w = 8 * ((pb >> 1) & 1) + 2 * (pb >> 2) + (pb & 1);
            int m = mbase + w;
            float2 xm = sx[m + (m >> 4)];
            float sqm = xm.x * xm.x + xm.y * xm.y;
            float dot = xn.x * xm.x + xn.y * xm.y;
            float d2 = sqn + sqm - 2.f * dot;
            float d = (d2 > 0.f) ? fast_sqrt(d2) : 0.f;
            acc += d;
            dval[cc] = (m == n) ? d + 1.0f : d;
        }
        __half2 hh = __floats2half2_rn(dval[0], dval[1]);
        ov[pp] = *(uint32_t*)&hh;
    }
    *(uint4*)(drow + mbase + 8 * half) = make_uint4(ov[0], ov[1], ov[2], ov[3]);

    red[t] = acc;
    __syncthreads();
    for (int s = 128; s > 0; s >>= 1) {
        if (t < s) red[t] += red[t + s];
        __syncthreads();
    }
    if (t == 0)
        g_dinv[b * NN + n] = rsqrtf(1.0f + red[0]);
}

// ---------------------------------------------------------------------------
// Kernel 3 (fp16 MMA, output-major, 128-row m-tiles, grid 128, 512 threads):
//   zT[b][e][m] = dinv[m] * sum_d Wg[e,d] * hn[m,d]
// mode 0: h = inst@Wn^T+bn during staging; mode 1: inline stats finalize +
// GraphNorm applied during staging, normalized h written back.
// ---------------------------------------------------------------------------
__global__ void __launch_bounds__(512) k_z(float* __restrict__ h,
                                           const float* __restrict__ Wg,
                                           int mode,
                                           const float* __restrict__ gnw,
                                           const float* __restrict__ gnb,
                                           const float* __restrict__ gna,
                                           const float* __restrict__ inst,
                                           const float* __restrict__ Wn,
                                           const float* __restrict__ bn) {
    extern __shared__ char smc[];
    uint32_t sbase = smem_u32(smc);
    uint32_t as_ = sbase + ZA_OFF, bs_ = sbase + ZB_OFF;
    float* smean = (float*)(smc + ZST_OFF);
    float* srstd = (float*)(smc + ZST_OFF + 512);
    int t = threadIdx.x, l = t & 31, wid = t >> 5;
    int wm = wid & 3, wn = wid >> 2;
    int row0 = blockIdx.x * 128;
    int b = row0 >> 11;
    int m0g = row0 & (NN - 1);

    if (mode == 1) {
        if (t < 128) {
            float s = 0.f, q = 0.f;
#pragma unroll
            for (int tile = 0; tile < NTILES; tile++) {
                float2 v = g_part[((size_t)b * NTILES + tile) * ND + t];
                s += v.x; q += v.y;
            }
            float mean = s * (1.f / NN);
            float eh2 = q * (1.f / NN);
            float a = gna[t];
            float var = eh2 - (2.f * a - a * a) * mean * mean;
            smean[t] = mean;
            srstd[t] = rsqrtf(var + 1e-5f);
        }
        __syncthreads();
    }

    float4 wbuf[8];
    float4 hbuf[8];
#pragma unroll
    for (int q = 0; q < 8; q++) {
        int idx = q * 512 + t;
        wbuf[q] = *(const float4*)&Wg[(idx >> 5) * ND + 4 * (idx & 31)];
    }
    if (mode == 0) {
#pragma unroll
        for (int q = 0; q < 8; q++) {
            int idx = q * 512 + t;
            int grow = row0 + (idx >> 5), u = idx & 31;
            float2 x = ((const float2*)inst)[grow];
#pragma unroll
            for (int j = 0; j < 4; j++) {
                int d = 4 * u + j;
                ((float*)&hbuf[q])[j] = x.x * Wn[2 * d] + x.y * Wn[2 * d + 1] + bn[d];
            }
        }
    } else {
#pragma unroll
        for (int q = 0; q < 8; q++) {
            int idx = q * 512 + t;
            hbuf[q] = *(const float4*)&h[(size_t)(row0 + (idx >> 5)) * ND + 4 * (idx & 31)];
        }
    }

#pragma unroll
    for (int q = 0; q < 8; q++) {
        int idx = q * 512 + t;
        int r = idx >> 5, u = idx & 31;
        int blk = u >> 2;
        int p0 = 2 * (u & 3), p1 = p0 + 1;
        int s0 = (p0 < 4) ? 2 * p0 : 2 * (p0 - 4) + 1;
        int s1 = (p1 < 4) ? 2 * p1 : 2 * (p1 - 4) + 1;
        uint32_t base = (uint32_t)(r * ZROWB + blk * 32);
        *(__half2*)(smc + ZA_OFF + base + s0 * 4) = __floats2half2_rn(wbuf[q].x, wbuf[q].y);
        *(__half2*)(smc + ZA_OFF + base + s1 * 4) = __floats2half2_rn(wbuf[q].z, wbuf[q].w);
    }
#pragma unroll
    for (int q = 0; q < 8; q++) {
        int idx = q * 512 + t;
        int r = idx >> 5, u = idx & 31;
        int grow = row0 + r;
        float4 hv = hbuf[q];
        if (mode == 1) {
            float4 mw = *(const float4*)&smean[4 * u];
            float4 rw = *(const float4*)&srstd[4 * u];
            float4 w_ = *(const float4*)&gnw[4 * u];
            float4 b_ = *(const float4*)&gnb[4 * u];
            float4 a_ = *(const float4*)&gna[4 * u];
            hv.x = w_.x * (hv.x - a_.x * mw.x) * rw.x + b_.x;
            hv.y = w_.y * (hv.y - a_.y * mw.y) * rw.y + b_.y;
            hv.z = w_.z * (hv.z - a_.z * mw.z) * rw.z + b_.z;
            hv.w = w_.w * (hv.w - a_.w * mw.w) * rw.w + b_.w;
        }
        *(float4*)&h[(size_t)grow * ND + 4 * u] = hv;
        int blk = u >> 2;
        int p0 = 2 * (u & 3), p1 = p0 + 1;
        int s0 = (p0 < 4) ? 2 * p0 : 2 * (p0 - 4) + 1;
        int s1 = (p1 < 4) ? 2 * p1 : 2 * (p1 - 4) + 1;
        uint32_t base = (uint32_t)(r * ZROWB + blk * 32);
        *(__half2*)(smc + ZB_OFF + base + s0 * 4) = __floats2half2_rn(hv.x, hv.y);
        *(__half2*)(smc + ZB_OFF + base + s1 * 4) = __floats2half2_rn(hv.z, hv.w);
    }
    __syncthreads();

    float c[2][4][4];
#pragma unroll
    for (int i = 0; i < 2; i++)
#pragma unroll
        for (int j = 0; j < 4; j++)
#pragma unroll
            for (int k = 0; k < 4; k++) c[i][j][k] = 0.f;

#pragma unroll
    for (int s = 0; s < 8; s++) {
        uint32_t bf[4][2];
#pragma unroll
        for (int nt = 0; nt < 4; nt++) {
            int nrow = wn * 32 + nt * 8 + (l >> 2);
            asm volatile("ld.shared.v2.b32 {%0,%1}, [%2];"
                         : "=r"(bf[nt][0]), "=r"(bf[nt][1])
                         : "r"(bs_ + (uint32_t)(nrow * ZROWB + s * 32 + (l & 3) * 8)));
        }
#pragma unroll
        for (int mt = 0; mt < 2; mt++) {
            uint32_t af[4];
            int mrow = wm * 32 + mt * 16 + (l >> 2);
            asm volatile("ld.shared.v2.b32 {%0,%1}, [%2];"
                         : "=r"(af[0]), "=r"(af[2])
                         : "r"(as_ + (uint32_t)(mrow * ZROWB + s * 32 + (l & 3) * 8)));
            asm volatile("ld.shared.v2.b32 {%0,%1}, [%2];"
                         : "=r"(af[1]), "=r"(af[3])
                         : "r"(as_ + (uint32_t)((mrow + 8) * ZROWB + s * 32 + (l & 3) * 8)));
#pragma unroll
            for (int nt = 0; nt < 4; nt++) {
                asm volatile(
                    "mma.sync.aligned.m16n8k16.row.col.f32.f16.f16.f32 "
                    "{%0,%1,%2,%3}, {%4,%5,%6,%7}, {%8,%9}, {%0,%1,%2,%3};"
                    : "+f"(c[mt][nt][0]), "+f"(c[mt][nt][1]),
                      "+f"(c[mt][nt][2]), "+f"(c[mt][nt][3])
                    : "r"(af[0]), "r"(af[1]), "r"(af[2]), "r"(af[3]),
                      "r"(bf[nt][0]), "r"(bf[nt][1]));
            }
        }
    }

    float2 dv[4];
#pragma unroll
    for (int nt = 0; nt < 4; nt++)
        dv[nt] = *(const float2*)&g_dinv[b * NN + m0g + wn * 32 + nt * 8 + 2 * (l & 3)];

    __syncthreads();
#pragma unroll
    for (int mt = 0; mt < 2; mt++) {
        int e0 = wm * 32 + mt * 16 + (l >> 2);
#pragma unroll
        for (int nt = 0; nt < 4; nt++) {
            int mloc = wn * 32 + nt * 8 + 2 * (l & 3);
            int phys = (mloc & ~15) + kperm(mloc & 15);
            *(__half2*)(smc + ZA_OFF + (uint32_t)(e0 * ZROWB + phys * 2)) =
                __floats2half2_rn(c[mt][nt][0] * dv[nt].x, c[mt][nt][1] * dv[nt].y);
            *(__half2*)(smc + ZA_OFF + (uint32_t)((e0 + 8) * ZROWB + phys * 2)) =
                __floats2half2_rn(c[mt][nt][2] * dv[nt].x, c[mt][nt][3] * dv[nt].y);
        }
    }
    __syncthreads();

    __half* zTb = g_zT + (size_t)b * ND * NN;
#pragma unroll
    for (int it = 0; it < 4; it++) {
        int idx = it * 512 + t;
        int e = idx >> 4, ch = idx & 15;
        uint4 v = *(const uint4*)(smc + ZA_OFF + (uint32_t)(e * ZROWB + ch * 16));
        *(uint4*)(zTb + (size_t)e * NN + m0g + ch * 8) = v;
    }
}

// ---------------------------------------------------------------------------
// Kernel 4: fp16 m16n8k16 mma.sync GEMM, BK=128 (16 chunks: half the per-chunk
// overhead of BK=64), 3-stage cp.async, 288B rows, 256 threads (8 warps 2x4,
// warp tile 64x32) + fused stats partials.
// h[n,:] = tanh( dinv[n]*((dist+I)[n,:] @ z) + bg ) + h[n,:]
// ---------------------------------------------------------------------------
__global__ void __launch_bounds__(256) k_gemm_mma(float* __restrict__ h,
                                                  const float* __restrict__ bg_l) {
    extern __shared__ char smc[];
    uint32_t sbase = smem_u32(smc);
    int t = threadIdx.x, l = t & 31, wid = t >> 5;
    int wm = wid & 1, wn = wid >> 1;
    int b = blockIdx.y, n0 = blockIdx.x * 128;
    const __half* Ab = g_dist + ((size_t)b * NN + n0) * NN;
    const __half* Bt = g_zT + (size_t)b * ND * NN;

    float c[4][4][4];
#pragma unroll
    for (int i = 0; i < 4; i++)
#pragma unroll
        for (int j = 0; j < 4; j++)
#pragma unroll
            for (int k = 0; k < 4; k++) c[i][j][k] = 0.f;

#define LOADT(P, K0)                                                             \
    {                                                                            \
        uint32_t xas = sbase + (P) * STAGEB;                                     \
        uint32_t xbs = xas + 128u * ROWB;                                        \
        _Pragma("unroll")                                                        \
        for (int q = 0; q < 8; q++) {                                            \
            int idx = q * 256 + t;                                               \
            int r_ = idx >> 4;                                                   \
            int c16 = idx & 15;                                                  \
            uint32_t so = (uint32_t)(r_ * ROWB + c16 * 16);                      \
            asm volatile("cp.async.cg.shared.global [%0], [%1], 16;"             \
                         :: "r"(xas + so), "l"(Ab + (size_t)r_ * NN + (K0) + c16 * 8)); \
            asm volatile("cp.async.cg.shared.global [%0], [%1], 16;"             \
                         :: "r"(xbs + so), "l"(Bt + (size_t)r_ * NN + (K0) + c16 * 8)); \
        }                                                                        \
        asm volatile("cp.async.commit_group;");                                  \
    }

#define COMPUTE(P)                                                               \
    {                                                                            \
        uint32_t as_ = sbase + (P) * STAGEB;                                     \
        uint32_t bs_ = as_ + 128u * ROWB;                                        \
        _Pragma("unroll")                                                        \
        for (int s = 0; s < 8; s++) {                                            \
            uint32_t bf[4][2];                                                   \
            _Pragma("unroll")                                                    \
            for (int nt = 0; nt < 4; nt++) {                                     \
                int nrow = wn * 32 + nt * 8 + (l >> 2);                          \
                asm volatile("ld.shared.v2.b32 {%0,%1}, [%2];"                   \
                             : "=r"(bf[nt][0]), "=r"(bf[nt][1])                  \
                             : "r"(bs_ + (uint32_t)(nrow * ROWB + s * 32 + (l & 3) * 8))); \
            }                                                                    \
            _Pragma("unroll")                                                    \
            for (int mt = 0; mt < 4; mt++) {                                     \
                uint32_t af[4];                                                  \
                int mrow = wm * 64 + mt * 16 + (l >> 2);                         \
                asm volatile("ld.shared.v2.b32 {%0,%1}, [%2];"                   \
                             : "=r"(af[0]), "=r"(af[2])                          \
                             : "r"(as_ + (uint32_t)(mrow * ROWB + s * 32 + (l & 3) * 8))); \
                asm volatile("ld.shared.v2.b32 {%0,%1}, [%2];"                   \
                             : "=r"(af[1]), "=r"(af[3])                          \
                             : "r"(as_ + (uint32_t)((mrow + 8) * ROWB + s * 32 + (l & 3) * 8))); \
                _Pragma("unroll")                                                \
                for (int nt = 0; nt < 4; nt++) {                                 \
                    asm volatile(                                                \
                        "mma.sync.aligned.m16n8k16.row.col.f32.f16.f16.f32 "     \
                        "{%0,%1,%2,%3}, {%4,%5,%6,%7}, {%8,%9}, {%0,%1,%2,%3};"  \
                        : "+f"(c[mt][nt][0]), "+f"(c[mt][nt][1]),                \
                          "+f"(c[mt][nt][2]), "+f"(c[mt][nt][3])                 \
                        : "r"(af[0]), "r"(af[1]), "r"(af[2]), "r"(af[3]),        \
                          "r"(bf[nt][0]), "r"(bf[nt][1]));                       \
                }                                                                \
            }                                                                    \
        }                                                                        \
    }

    LOADT(0, 0);
    LOADT(1, BK);
    int p = 0;
    for (int it = 0; it < NIT; it++) {
        if (it + 1 < NIT)
            asm volatile("cp.async.wait_group 1;");
        else
            asm volatile("cp.async.wait_group 0;");
        __syncthreads();
        if (it + 2 < NIT) {
            int pn = (it + 2) % 3;
            LOADT(pn, (it + 2) * BK);
        }
        COMPUTE(p);
        p = (p + 1) % 3;
    }

    // epilogue: dinv + bias + tanh + residual, accumulating stats partials
    float ssum[8], ssq[8];
#pragma unroll
    for (int j = 0; j < 8; j++) { ssum[j] = 0.f; ssq[j] = 0.f; }
#pragma unroll
    for (int mt = 0; mt < 4; mt++) {
        int r0 = n0 + wm * 64 + mt * 16 + (l >> 2);
        int r1 = r0 + 8;
        float dv0 = g_dinv[b * NN + r0];
        float dv1 = g_dinv[b * NN + r1];
#pragma unroll
        for (int nt = 0; nt < 4; nt++) {
            int cc = wn * 32 + nt * 8 + 2 * (l & 3);
            float bg0 = bg_l[cc], bg1 = bg_l[cc + 1];
            size_t h0o = ((size_t)b * NN + r0) * ND + cc;
            size_t h1o = ((size_t)b * NN + r1) * ND + cc;
            float2 hv0 = *(const float2*)&h[h0o];
            float2 hv1 = *(const float2*)&h[h1o];
            float2 o0, o1;
            o0.x = tanhf(dv0 * c[mt][nt][0] + bg0) + hv0.x;
            o0.y = tanhf(dv0 * c[mt][nt][1] + bg1) + hv0.y;
            o1.x = tanhf(dv1 * c[mt][nt][2] + bg0) + hv1.x;
            o1.y = tanhf(dv1 * c[mt][nt][3] + bg1) + hv1.y;
            *(float2*)&h[h0o] = o0;
            *(float2*)&h[h1o] = o1;
            ssum[2 * nt]     += o0.x + o1.x;
            ssum[2 * nt + 1] += o0.y + o1.y;
            ssq[2 * nt]      += o0.x * o0.x + o1.x * o1.x;
            ssq[2 * nt + 1]  += o0.y * o0.y + o1.y * o1.y;
        }
    }
#pragma unroll
    for (int off = 4; off < 32; off <<= 1)
#pragma unroll
        for (int j = 0; j < 8; j++) {
            ssum[j] += __shfl_xor_sync(0xffffffffu, ssum[j], off);
            ssq[j]  += __shfl_xor_sync(0xffffffffu, ssq[j], off);
        }
    __syncthreads();
    float* sp = (float*)smc;
    if ((l >> 2) == 0) {
#pragma unroll
        for (int j = 0; j < 8; j++) {
            int col = wn * 32 + (j >> 1) * 8 + 2 * (l & 3) + (j & 1);
            sp[wm * 128 + col] = ssum[j];
            sp[256 + wm * 128 + col] = ssq[j];
        }
    }
    __syncthreads();
    if (t < 128) {
        float s = sp[t] + sp[128 + t];
        float q = sp[256 + t] + sp[384 + t];
        g_part[((size_t)b * NTILES + blockIdx.x) * ND + t] = make_float2(s, q);
    }
#undef LOADT
#undef COMPUTE
}

// ---------------------------------------------------------------------------
// Kernel 6: final GraphNorm (inline stats finalize + normalize), grid (32, NB)
// ---------------------------------------------------------------------------
__global__ void __launch_bounds__(512) k_norm(float* __restrict__ h,
                                              const float* __restrict__ gnw,
                                              const float* __restrict__ gnb,
                                              const float* __restrict__ gna) {
    __shared__ float smean[128], srstd[128];
    int b = blockIdx.y;
    int t = threadIdx.x;
    if (t < 128) {
        float s = 0.f, q = 0.f;
#pragma unroll
        for (int tile = 0; tile < NTILES; tile++) {
            float2 v = g_part[((size_t)b * NTILES + tile) * ND + t];
            s += v.x; q += v.y;
        }
        float mean = s * (1.f / NN);
        float eh2 = q * (1.f / NN);
        float a = gna[t];
        float var = eh2 - (2.f * a - a * a) * mean * mean;
        smean[t] = mean;
        srstd[t] = rsqrtf(var + 1e-5f);
    }
    __syncthreads();
    int row0 = blockIdx.x * 64;   // 64 rows per block
#pragma unroll
    for (int q = 0; q < 4; q++) {
        int idx = q * 512 + t;     // 2048 float4 = 64 rows x 32
        int r = idx >> 5, u = idx & 31;
        size_t off = ((size_t)b * NN + row0 + r) * ND + 4 * u;
        float4 hv = *(const float4*)&h[off];
        float4 mw = *(const float4*)&smean[4 * u];
        float4 rw = *(const float4*)&srstd[4 * u];
        float4 w_ = *(const float4*)&gnw[4 * u];
        float4 b_ = *(const float4*)&gnb[4 * u];
        float4 a_ = *(const float4*)&gna[4 * u];
        hv.x = w_.x * (hv.x - a_.x * mw.x) * rw.x + b_.x;
        hv.y = w_.y * (hv.y - a_.y * mw.y) * rw.y + b_.y;
        hv.z = w_.z * (hv.z - a_.z * mw.z) * rw.z + b_.z;
        hv.w = w_.w * (hv.w - a_.w * mw.w) * rw.w + b_.w;
        *(float4*)&h[off] = hv;
    }
}

// ---------------------------------------------------------------------------
extern "C" void kernel_launch(void* const* d_in, const int* in_sizes, int n_in,
                              void* d_out, int out_size) {
    const float* inst = (const float*)d_in[0];
    const float* Wn   = (const float*)d_in[1];
    const float* bn   = (const float*)d_in[2];
    const float* Wg   = (const float*)d_in[3];
    const float* bg   = (const float*)d_in[4];
    const float* gnw  = (const float*)d_in[5];
    const float* gnb  = (const float*)d_in[6];
    const float* gna  = (const float*)d_in[7];
    float* h = (float*)d_out;

    const int SMEM_GEMM = 3 * (int)STAGEB;   // 221184
    const int SMEM_Z    = (int)ZSMEM;        // 74752
    static int smem_set = 0;
    if (!smem_set) {
        cudaFuncSetAttribute(k_gemm_mma, cudaFuncAttributeMaxDynamicSharedMemorySize, SMEM_GEMM);
        cudaFuncSetAttribute(k_z, cudaFuncAttributeMaxDynamicSharedMemorySize, SMEM_Z);
        smem_set = 1;
    }

    k_dist<<<dim3(NN, NB), 256>>>(inst);
    for (int l = 0; l < 3; l++) {
        k_z<<<NB * NN / 128, 512, SMEM_Z>>>(h, Wg + l * ND * ND,
                                            l == 0 ? 0 : 1, gnw, gnb, gna,
                                            inst, Wn, bn);
        k_gemm_mma<<<dim3(NTILES, NB), 256, SMEM_GEMM>>>(h, bg + l * ND);
    }
    k_norm<<<dim3(32, NB), 512>>>(h, gnw, gnb, gna);
}